// round 13
// baseline (speedup 1.0000x reference)
#include <cuda_runtime.h>
#include <math.h>
#include <stdint.h>

#define N_NODES 50000
#define E_EDGES 800000
#define E_TOT   (E_EDGES + N_NODES)
#define IN_CH 128
#define H1C 200
#define H2C 100
#define OUTC 2

#define GEMM1_NCT    4
#define GEMM1_NRT    391
#define GEMM1_BLOCKS (GEMM1_NCT * GEMM1_NRT)
#define COUNT_BLOCKS 3125
#define GEMM2_NCT    2
#define GEMM2_BLOCKS (GEMM2_NCT * GEMM1_NRT)
#define FILL_BLOCKS  3321
#define NODE_BLOCKS  12500                  // 50000 warps / 4 (128-thread blocks)
#define WNODE_BLOCKS 6250                   // 50000 warps / 8 (256-thread blocks)
#define SCAN_BLOCKS  196

#define MASK1_WORDS  (N_NODES * H1C / 32)   // 312500
#define MASK2_WORDS  (N_NODES * H2C / 32)   // 156250
#define MASK1_BLOCKS ((MASK1_WORDS + 255) / 256)  // 1221 (8 warps x 32 words each)
#define MASK2_BLOCKS ((MASK2_WORDS + 255) / 256)  // 611

// ---------------- scratch (static __device__, zero-initialized) ----------------
__device__ float g_h[(size_t)N_NODES * H1C];
__device__ float g_buf[(size_t)N_NODES * H1C];
__device__ float g_ss1[N_NODES];            // reset by k_node1
__device__ float g_ss2[N_NODES];            // reset by k_gemm3_norm
__device__ float g_invn[N_NODES];           // layer-1 invn (scan1), then layer-3
__device__ int   g_deg[N_NODES];            // reset by k_fill
__device__ int   g_rowptr[N_NODES + 1];
__device__ int   g_cursor[N_NODES];         // reset by k_node1
__device__ int   g_csrsrc[E_TOT];
__device__ int   g_bsum[256];               // overwritten by scan1 each run
__device__ uint32_t g_mask1[MASK1_WORDS];   // overwritten each run
__device__ uint32_t g_mask2[MASK2_WORDS];   // overwritten each run

// ---------------- Threefry-2x32 (matches JAX, confirmed) ----------------
__host__ __device__ inline uint32_t rotl32(uint32_t v, int d) {
    return (v << d) | (v >> (32 - d));
}
__host__ __device__ inline void threefry2x32(uint32_t key0, uint32_t key1,
                                             uint32_t x0, uint32_t x1,
                                             uint32_t& o0, uint32_t& o1) {
    uint32_t ks[3] = {key0, key1, key0 ^ key1 ^ 0x1BD11BDAu};
    const int rot[8] = {13, 15, 26, 6, 17, 29, 16, 24};
    x0 += ks[0]; x1 += ks[1];
#pragma unroll
    for (int i = 0; i < 5; i++) {
        const int* r = &rot[(i & 1) * 4];
#pragma unroll
        for (int j = 0; j < 4; j++) { x0 += x1; x1 = rotl32(x1, r[j]); x1 ^= x0; }
        x0 += ks[(i + 1) % 3];
        x1 += ks[(i + 2) % 3] + (uint32_t)(i + 1);
    }
    o0 = x0; o1 = x1;
}

// Warp-cooperative dropout-mask generation: warp covers 32 words; per round,
// each lane hashes one element of word w, ballot assembles the word.
__device__ __forceinline__ void gen_mask(uint32_t* mask, int nwords, int gwarp,
                                         int lane, uint32_t k0, uint32_t k1) {
    int base = gwarp * 32;
    if (base >= nwords) return;
    uint32_t myword = 0;
#pragma unroll 4
    for (int k = 0; k < 32; k++) {
        uint32_t idx = (uint32_t)(base + k) * 32u + (uint32_t)lane;
        uint32_t o0, o1;
        threefry2x32(k0, k1, 0u, idx, o0, o1);
        uint32_t bits = o0 ^ o1;
        float u = __uint_as_float((bits >> 9) | 0x3f800000u) - 1.0f;
        uint32_t b = __ballot_sync(0xffffffffu, u < 0.9f);
        if (lane == k) myword = b;
    }
    if (base + lane < nwords) mask[base + lane] = myword;
}

// ---------------- cp.async helpers ----------------
__device__ __forceinline__ void cp_async16(void* smem_dst, const void* gsrc, bool valid) {
    uint32_t saddr = (uint32_t)__cvta_generic_to_shared(smem_dst);
    int bytes = valid ? 16 : 0;
    asm volatile("cp.async.cg.shared.global [%0], [%1], 16, %2;\n"
                 :: "r"(saddr), "l"(gsrc), "r"(bytes));
}
#define CP_COMMIT()  asm volatile("cp.async.commit_group;\n")
#define CP_WAIT(n)   asm volatile("cp.async.wait_group %0;\n" :: "n"(n))

// ---------------- tf32 helpers ----------------
__device__ __forceinline__ uint32_t f2tf32(float f) {
    uint32_t o;
    asm volatile("cvt.rna.tf32.f32 %0, %1;" : "=r"(o) : "f"(f));
    return o;
}
__device__ __forceinline__ void split_tf32(float f, uint32_t& hi, uint32_t& lo) {
    hi = f2tf32(f);
    lo = f2tf32(f - __uint_as_float(hi));
}
__device__ __forceinline__ void mma_tf32(float* c, const uint32_t* a, const uint32_t* b) {
    asm volatile(
        "mma.sync.aligned.m16n8k8.row.col.f32.tf32.tf32.f32 "
        "{%0,%1,%2,%3}, {%4,%5,%6,%7}, {%8,%9}, {%0,%1,%2,%3};\n"
        : "+f"(c[0]), "+f"(c[1]), "+f"(c[2]), "+f"(c[3])
        : "r"(a[0]), "r"(a[1]), "r"(a[2]), "r"(a[3]), "r"(b[0]), "r"(b[1]));
}

// ---------------- 3xTF32 GEMM body + fused row-sumsq epilogue ----------------
#define AST 36
#define BST 72
template <int SRC>
__device__ __forceinline__ void gemm_body(const float* __restrict__ Aext,
                                          const float* __restrict__ B,
                                          float* __restrict__ ss,
                                          int M, int N, int K,
                                          int bx, int nColTiles) {
    const float* A = (SRC == 0) ? Aext : g_buf;
    __shared__ __align__(16) float AsF[2][128 * AST];
    __shared__ __align__(16) float BsF[2][32 * BST];
    const int tid = threadIdx.x;
    const int wid = tid >> 5, lane = tid & 31;
    const int g = lane >> 2, t = lane & 3;
    const int warpM = wid >> 1, warpN = wid & 1;
    const int rowBase = (bx / nColTiles) * 128, colBase = (bx % nColTiles) * 64;

    auto issue = [&](int ch, int buf) {
        const int k0 = ch * 32;
#pragma unroll
        for (int i = 0; i < 4; i++) {
            int f = tid + i * 256;
            int r = f >> 3, c4 = f & 7;
            int gr = rowBase + r, gk = k0 + c4 * 4;
            bool ok = (gr < M) && (gk < K);
            const float* src = ok ? (A + (size_t)gr * K + gk) : A;
            cp_async16(&AsF[buf][r * AST + c4 * 4], src, ok);
        }
#pragma unroll
        for (int i = 0; i < 2; i++) {
            int f = tid + i * 256;
            int r = f >> 4, c4 = f & 15;
            int gk = k0 + r, gn = colBase + c4 * 4;
            bool ok = (gk < K) && (gn < N);
            const float* src = ok ? (B + (size_t)gk * N + gn) : B;
            cp_async16(&BsF[buf][r * BST + c4 * 4], src, ok);
        }
        CP_COMMIT();
    };

    float acc[2][4][4];
#pragma unroll
    for (int mt = 0; mt < 2; mt++)
#pragma unroll
        for (int nt = 0; nt < 4; nt++)
#pragma unroll
            for (int r = 0; r < 4; r++) acc[mt][nt][r] = 0.f;

    const int nCh = (K + 31) / 32;
    issue(0, 0);
    for (int ch = 0; ch < nCh; ch++) {
        const int cur = ch & 1;
        if (ch + 1 < nCh) { issue(ch + 1, cur ^ 1); CP_WAIT(1); }
        else              { CP_WAIT(0); }
        __syncthreads();
#pragma unroll
        for (int kk = 0; kk < 4; kk++) {
            const int kl = kk * 8;
            uint32_t aH[2][4], aL[2][4];
#pragma unroll
            for (int mt = 0; mt < 2; mt++) {
                int m0 = warpM * 32 + mt * 16 + g;
                float a0 = AsF[cur][m0 * AST + kl + t];
                float a1 = AsF[cur][(m0 + 8) * AST + kl + t];
                float a2 = AsF[cur][m0 * AST + kl + t + 4];
                float a3 = AsF[cur][(m0 + 8) * AST + kl + t + 4];
                split_tf32(a0, aH[mt][0], aL[mt][0]);
                split_tf32(a1, aH[mt][1], aL[mt][1]);
                split_tf32(a2, aH[mt][2], aL[mt][2]);
                split_tf32(a3, aH[mt][3], aL[mt][3]);
            }
#pragma unroll
            for (int nt = 0; nt < 4; nt++) {
                int n0 = warpN * 32 + nt * 8 + g;
                float b0 = BsF[cur][(kl + t) * BST + n0];
                float b1 = BsF[cur][(kl + t + 4) * BST + n0];
                uint32_t bH[2], bL[2];
                split_tf32(b0, bH[0], bL[0]);
                split_tf32(b1, bH[1], bL[1]);
#pragma unroll
                for (int mt = 0; mt < 2; mt++) {
                    mma_tf32(acc[mt][nt], aH[mt], bL);
                    mma_tf32(acc[mt][nt], aL[mt], bH);
                    mma_tf32(acc[mt][nt], aH[mt], bH);
                }
            }
        }
        __syncthreads();
    }
#pragma unroll
    for (int mt = 0; mt < 2; mt++) {
#pragma unroll
        for (int half = 0; half < 2; half++) {
            int m = rowBase + warpM * 32 + mt * 16 + g + half * 8;
            float ssp = 0.f;
#pragma unroll
            for (int nt = 0; nt < 4; nt++) {
                int n = colBase + warpN * 32 + nt * 8 + t * 2;
                if (n < N && m < M) {
                    float c0 = acc[mt][nt][half * 2], c1 = acc[mt][nt][half * 2 + 1];
                    *reinterpret_cast<float2*>(g_h + (size_t)m * N + n) = make_float2(c0, c1);
                    ssp += c0 * c0 + c1 * c1;
                }
            }
            ssp += __shfl_xor_sync(0xffffffffu, ssp, 1);
            ssp += __shfl_xor_sync(0xffffffffu, ssp, 2);
            if (t == 0 && m < M) atomicAdd(&ss[m], ssp);
        }
    }
}

// ---------------- kernels ----------------
// fused: [GEMM1 (+ss1) | edge count | mask1 generation]
__global__ void __launch_bounds__(256) k_gemm1_count(const float* __restrict__ x,
                                                     const float* __restrict__ W1,
                                                     const int* __restrict__ dst,
                                                     uint32_t k1a, uint32_t k1b) {
    if (blockIdx.x < GEMM1_BLOCKS) {
        gemm_body<0>(x, W1, g_ss1, N_NODES, H1C, IN_CH, blockIdx.x, GEMM1_NCT);
    } else if (blockIdx.x < GEMM1_BLOCKS + COUNT_BLOCKS) {
        int e = (blockIdx.x - GEMM1_BLOCKS) * 256 + threadIdx.x;
        if (e < E_EDGES) atomicAdd(&g_deg[dst[e]], 1);
    } else {
        int gwarp = (blockIdx.x - GEMM1_BLOCKS - COUNT_BLOCKS) * 8 + (threadIdx.x >> 5);
        gen_mask(g_mask1, MASK1_WORDS, gwarp, threadIdx.x & 31, k1a, k1b);
    }
}

// scan1: local prefix + block sums; also ss1 -> invn (layer-1 norms).
__global__ void k_scan1() {
    __shared__ int sh[256];
    int b = blockIdx.x, t = threadIdx.x, i = b * 256 + t;
    int v = (i < N_NODES) ? (g_deg[i] + 1) : 0;   // +1 = self-loop
    if (i < N_NODES) g_invn[i] = rsqrtf(fmaxf(g_ss1[i], 1e-24f));
    sh[t] = v;
    __syncthreads();
    for (int off = 1; off < 256; off <<= 1) {
        int x = (t >= off) ? sh[t - off] : 0;
        __syncthreads();
        sh[t] += x;
        __syncthreads();
    }
    if (i < N_NODES) g_rowptr[i] = sh[t] - v;
    if (t == 255) g_bsum[b] = sh[255];
}
__global__ void k_scan3() {
    __shared__ int sh[256];
    int t = threadIdx.x, b = blockIdx.x;
    sh[t] = (t < b) ? g_bsum[t] : 0;
    __syncthreads();
    for (int s = 128; s; s >>= 1) {
        if (t < s) sh[t] += sh[t + s];
        __syncthreads();
    }
    int off = sh[0];
    int i = b * 256 + t;
    if (i < N_NODES) g_rowptr[i] += off;
    if (i == 0) g_rowptr[N_NODES] = E_TOT;
}

// fused: [CSR fill (+deg reset) | mask2 generation]
__global__ void k_fill(const int* __restrict__ src, const int* __restrict__ dst,
                       uint32_t k2a, uint32_t k2b) {
    if (blockIdx.x < FILL_BLOCKS) {
        int e = blockIdx.x * 256 + threadIdx.x;
        if (e < N_NODES) g_deg[e] = 0;
        if (e >= E_TOT) return;
        int s, d;
        if (e < E_EDGES) { s = src[e]; d = dst[e]; }
        else             { s = e - E_EDGES; d = s; }
        int pos = atomicAdd(&g_cursor[d], 1);
        g_csrsrc[g_rowptr[d] + pos] = s;
    } else {
        int gwarp = (blockIdx.x - FILL_BLOCKS) * 8 + (threadIdx.x >> 5);
        gen_mask(g_mask2, MASK2_WORDS, gwarp, threadIdx.x & 31, k2a, k2b);
    }
}

__global__ void __launch_bounds__(256) k_gemm2(const float* __restrict__ W2) {
    gemm_body<1>(nullptr, W2, g_ss2, N_NODES, H2C, H1C, blockIdx.x, GEMM2_NCT);
}

// ---------------- fused attention + softmax + agg + relu + dropout ----------
// One warp per dst node; float4 row loads; unroll-2; 32-bit addressing.
// Dropout mask precomputed (bit per element). USE_INV: layer-1 invn array.
template <int D, bool USE_INV, bool RESET1>
__global__ void __launch_bounds__(128, 10) k_node(const float* __restrict__ beta_p) {
    const uint32_t* mask = USE_INV ? g_mask1 : g_mask2;
    int v = (blockIdx.x * blockDim.x + threadIdx.x) >> 5;
    int lane = threadIdx.x & 31;
    if (v >= N_NODES) return;
    constexpr int C4 = (D + 127) / 128;
    const float4 z4 = make_float4(0.f, 0.f, 0.f, 0.f);

    float4 hv[C4];
    int vbase = v * D;
#pragma unroll
    for (int c = 0; c < C4; c++) {
        int f0 = (c * 32 + lane) * 4;
        hv[c] = (f0 < D) ? *reinterpret_cast<const float4*>(g_h + vbase + f0) : z4;
    }
    float nvv = USE_INV ? g_invn[v] : rsqrtf(fmaxf(g_ss2[v], 1e-24f));
    float bi = __ldg(beta_p) * nvv;
    if (RESET1 && lane == 0) { g_cursor[v] = 0; g_ss1[v] = 0.f; }
    int e0 = g_rowptr[v], e1 = g_rowptr[v + 1];
    float denom = 0.0f;
    float4 acc[C4];
#pragma unroll
    for (int c = 0; c < C4; c++) acc[c] = z4;

    for (int e = e0; e < e1; e += 2) {
        bool hasB = (e + 1 < e1);
        int sA = g_csrsrc[e];
        int sB = hasB ? g_csrsrc[e + 1] : sA;
        float nA = USE_INV ? g_invn[sA] : rsqrtf(fmaxf(g_ss2[sA], 1e-24f));
        float nB = USE_INV ? g_invn[sB] : rsqrtf(fmaxf(g_ss2[sB], 1e-24f));
        int aBase = sA * D, bBase = sB * D;
        float4 hA[C4], hB[C4];
#pragma unroll
        for (int c = 0; c < C4; c++) {
            int f0 = (c * 32 + lane) * 4;
            bool ok = (f0 < D);
            hA[c] = ok ? *reinterpret_cast<const float4*>(g_h + aBase + f0) : z4;
            hB[c] = ok ? *reinterpret_cast<const float4*>(g_h + bBase + f0) : z4;
        }
        float dA = 0.f, dB = 0.f;
#pragma unroll
        for (int c = 0; c < C4; c++) {
            dA += hv[c].x * hA[c].x + hv[c].y * hA[c].y + hv[c].z * hA[c].z + hv[c].w * hA[c].w;
            dB += hv[c].x * hB[c].x + hv[c].y * hB[c].y + hv[c].z * hB[c].z + hv[c].w * hB[c].w;
        }
#pragma unroll
        for (int o = 16; o; o >>= 1) {
            dA += __shfl_xor_sync(0xffffffffu, dA, o);
            dB += __shfl_xor_sync(0xffffffffu, dB, o);
        }
        float wA = __expf(bi * dA * nA);
        float wB = hasB ? __expf(bi * dB * nB) : 0.0f;
        denom += wA + wB;
#pragma unroll
        for (int c = 0; c < C4; c++) {
            acc[c].x += wA * hA[c].x + wB * hB[c].x;
            acc[c].y += wA * hA[c].y + wB * hB[c].y;
            acc[c].z += wA * hA[c].z + wB * hB[c].z;
            acc[c].w += wA * hA[c].w + wB * hB[c].w;
        }
    }
    float dinv = 1.0f / fmaxf(denom, 1e-12f);
#pragma unroll
    for (int c = 0; c < C4; c++) {
        int f0 = (c * 32 + lane) * 4;
        if (f0 >= D) continue;
        uint32_t idx4 = (uint32_t)(vbase + f0);
        uint32_t word = mask[idx4 >> 5];
        uint32_t sh = idx4 & 31u;
        float vals[4] = {acc[c].x * dinv, acc[c].y * dinv, acc[c].z * dinv, acc[c].w * dinv};
        float4 o4;
        float* op = reinterpret_cast<float*>(&o4);
#pragma unroll
        for (int comp = 0; comp < 4; comp++) {
            float val = fmaxf(vals[comp], 0.0f);
            bool keep = (word >> (sh + comp)) & 1u;
            op[comp] = keep ? (val / 0.9f) : 0.0f;
        }
        *reinterpret_cast<float4*>(g_buf + vbase + f0) = o4;
    }
}

// ---------------- layer 3 dedicated path (D=2) ----------------
__global__ void k_gemm3_norm(const float* __restrict__ W3) {
    int v = (blockIdx.x * blockDim.x + threadIdx.x) >> 5;
    int lane = threadIdx.x & 31;
    if (v >= N_NODES) return;
    if (lane == 0) g_ss2[v] = 0.f;   // reset for replay
    float s0 = 0.f, s1 = 0.f;
#pragma unroll
    for (int j = 0; j < 4; j++) {
        int d = lane + 32 * j;
        if (d < H2C) {
            float hval = g_buf[v * H2C + d];
            s0 += hval * __ldg(W3 + d * 2 + 0);
            s1 += hval * __ldg(W3 + d * 2 + 1);
        }
    }
#pragma unroll
    for (int o = 16; o; o >>= 1) {
        s0 += __shfl_xor_sync(0xffffffffu, s0, o);
        s1 += __shfl_xor_sync(0xffffffffu, s1, o);
    }
    if (lane == 0) {
        g_h[v * 2 + 0] = s0;
        g_h[v * 2 + 1] = s1;
        g_invn[v] = 1.0f / fmaxf(sqrtf(s0 * s0 + s1 * s1), 1e-12f);
    }
}

__global__ void k_node3(const float* __restrict__ beta_p, float* __restrict__ out) {
    int v = blockIdx.x * blockDim.x + threadIdx.x;
    if (v >= N_NODES) return;
    const float2* h2 = reinterpret_cast<const float2*>(g_h);
    float2 hv = h2[v];
    float bi = __ldg(beta_p) * g_invn[v];
    int e0 = g_rowptr[v], e1 = g_rowptr[v + 1];
    float denom = 0.f, a0 = 0.f, a1 = 0.f;
    for (int e = e0; e < e1; e++) {
        int s = g_csrsrc[e];
        float2 hs = h2[s];
        float w = __expf(bi * (hv.x * hs.x + hv.y * hs.y) * g_invn[s]);
        denom += w;
        a0 += w * hs.x;
        a1 += w * hs.y;
    }
    float dinv = 1.0f / fmaxf(denom, 1e-12f);
    out[v * 2 + 0] = fmaxf(a0 * dinv, 0.f);
    out[v * 2 + 1] = fmaxf(a1 * dinv, 0.f);
}

extern "C" void kernel_launch(void* const* d_in, const int* in_sizes, int n_in,
                              void* d_out, int out_size) {
    const float* x  = (const float*)d_in[0];
    const int*   ei = (const int*)d_in[1];
    const float* W1 = (const float*)d_in[2];
    const float* W2 = (const float*)d_in[3];
    const float* W3 = (const float*)d_in[4];
    const float* b1 = (const float*)d_in[5];
    const float* b2 = (const float*)d_in[6];
    const float* b3 = (const float*)d_in[7];
    float* out = (float*)d_out;
    const int* src = ei;
    const int* dst = ei + E_EDGES;

    uint32_t k1a, k1b, k2a, k2b;
    threefry2x32(0u, 42u, 0u, 0u, k1a, k1b);
    threefry2x32(0u, 42u, 0u, 1u, k2a, k2b);

    k_gemm1_count<<<GEMM1_BLOCKS + COUNT_BLOCKS + MASK1_BLOCKS, 256>>>(x, W1, dst, k1a, k1b);
    k_scan1<<<SCAN_BLOCKS, 256>>>();
    k_scan3<<<SCAN_BLOCKS, 256>>>();
    k_fill<<<FILL_BLOCKS + MASK2_BLOCKS, 256>>>(src, dst, k2a, k2b);
    k_node<H1C, true, true><<<NODE_BLOCKS, 128>>>(b1);
    k_gemm2<<<GEMM2_BLOCKS, 256>>>(W2);
    k_node<H2C, false, false><<<NODE_BLOCKS, 128>>>(b2);
    k_gemm3_norm<<<WNODE_BLOCKS, 256>>>(W3);
    k_node3<<<SCAN_BLOCKS, 256>>>(b3, out);
    (void)in_sizes; (void)n_in; (void)out_size;
}

// round 14
// speedup vs baseline: 1.0166x; 1.0166x over previous
#include <cuda_runtime.h>
#include <math.h>
#include <stdint.h>

#define N_NODES 50000
#define E_EDGES 800000
#define E_TOT   (E_EDGES + N_NODES)
#define IN_CH 128
#define H1C 200
#define H2C 100
#define OUTC 2

#define GEMM1_NCT    4
#define GEMM1_NRT    391
#define GEMM1_BLOCKS (GEMM1_NCT * GEMM1_NRT)
#define COUNT_BLOCKS 3125
#define GEMM2_NCT    2
#define GEMM2_BLOCKS (GEMM2_NCT * GEMM1_NRT)
#define FILL_BLOCKS  3321
#define NODE_BLOCKS  12500                  // 50000 warps / 4 (128-thread blocks)
#define WNODE_BLOCKS 6250                   // 50000 warps / 8 (256-thread blocks)
#define SCAN_BLOCKS  196

#define MASK1_WORDS  (N_NODES * H1C / 32)   // 312500
#define MASK2_WORDS  (N_NODES * H2C / 32)   // 156250
#define MASK1_BLOCKS ((MASK1_WORDS + 255) / 256)  // 1221
#define MASK2_BLOCKS ((MASK2_WORDS + 255) / 256)  // 611

// ---------------- scratch (static __device__, zero-initialized) ----------------
__device__ float g_h[(size_t)N_NODES * H1C];
__device__ float g_buf[(size_t)N_NODES * H1C];
__device__ float g_ss1[N_NODES];            // reset by k_node1
__device__ float g_ss2[N_NODES];            // reset by k_gemm3_norm
__device__ float g_invn[N_NODES];           // layer-1 invn (scan1), then layer-3
__device__ int   g_deg[N_NODES];            // reset by k_fill
__device__ int   g_rowptr[N_NODES];         // LOCAL (per-block) prefix, from scan1
__device__ int   g_rowptr2[N_NODES + 1];    // FINAL rowptr, from k_fill
__device__ int   g_cursor[N_NODES];         // reset by k_node1
__device__ int   g_csrsrc[E_TOT];
__device__ int   g_bsum[256];               // overwritten by scan1 each run
__device__ uint32_t g_mask1[MASK1_WORDS];   // overwritten each run
__device__ uint32_t g_mask2[MASK2_WORDS];   // overwritten each run

// ---------------- Threefry-2x32 (matches JAX, confirmed) ----------------
__host__ __device__ inline uint32_t rotl32(uint32_t v, int d) {
    return (v << d) | (v >> (32 - d));
}
__host__ __device__ inline void threefry2x32(uint32_t key0, uint32_t key1,
                                             uint32_t x0, uint32_t x1,
                                             uint32_t& o0, uint32_t& o1) {
    uint32_t ks[3] = {key0, key1, key0 ^ key1 ^ 0x1BD11BDAu};
    const int rot[8] = {13, 15, 26, 6, 17, 29, 16, 24};
    x0 += ks[0]; x1 += ks[1];
#pragma unroll
    for (int i = 0; i < 5; i++) {
        const int* r = &rot[(i & 1) * 4];
#pragma unroll
        for (int j = 0; j < 4; j++) { x0 += x1; x1 = rotl32(x1, r[j]); x1 ^= x0; }
        x0 += ks[(i + 1) % 3];
        x1 += ks[(i + 2) % 3] + (uint32_t)(i + 1);
    }
    o0 = x0; o1 = x1;
}

// Warp-cooperative dropout-mask generation (semantics confirmed in R13).
__device__ __forceinline__ void gen_mask(uint32_t* mask, int nwords, int gwarp,
                                         int lane, uint32_t k0, uint32_t k1) {
    int base = gwarp * 32;
    if (base >= nwords) return;
    uint32_t myword = 0;
#pragma unroll 4
    for (int k = 0; k < 32; k++) {
        uint32_t idx = (uint32_t)(base + k) * 32u + (uint32_t)lane;
        uint32_t o0, o1;
        threefry2x32(k0, k1, 0u, idx, o0, o1);
        uint32_t bits = o0 ^ o1;
        float u = __uint_as_float((bits >> 9) | 0x3f800000u) - 1.0f;
        uint32_t b = __ballot_sync(0xffffffffu, u < 0.9f);
        if (lane == k) myword = b;
    }
    if (base + lane < nwords) mask[base + lane] = myword;
}

// ---------------- cp.async helpers ----------------
__device__ __forceinline__ void cp_async16(void* smem_dst, const void* gsrc, bool valid) {
    uint32_t saddr = (uint32_t)__cvta_generic_to_shared(smem_dst);
    int bytes = valid ? 16 : 0;
    asm volatile("cp.async.cg.shared.global [%0], [%1], 16, %2;\n"
                 :: "r"(saddr), "l"(gsrc), "r"(bytes));
}
#define CP_COMMIT()  asm volatile("cp.async.commit_group;\n")
#define CP_WAIT(n)   asm volatile("cp.async.wait_group %0;\n" :: "n"(n))

// ---------------- tf32 helpers ----------------
__device__ __forceinline__ uint32_t f2tf32(float f) {
    uint32_t o;
    asm volatile("cvt.rna.tf32.f32 %0, %1;" : "=r"(o) : "f"(f));
    return o;
}
__device__ __forceinline__ void split_tf32(float f, uint32_t& hi, uint32_t& lo) {
    hi = f2tf32(f);
    lo = f2tf32(f - __uint_as_float(hi));
}
__device__ __forceinline__ void mma_tf32(float* c, const uint32_t* a, const uint32_t* b) {
    asm volatile(
        "mma.sync.aligned.m16n8k8.row.col.f32.tf32.tf32.f32 "
        "{%0,%1,%2,%3}, {%4,%5,%6,%7}, {%8,%9}, {%0,%1,%2,%3};\n"
        : "+f"(c[0]), "+f"(c[1]), "+f"(c[2]), "+f"(c[3])
        : "r"(a[0]), "r"(a[1]), "r"(a[2]), "r"(a[3]), "r"(b[0]), "r"(b[1]));
}

// ---------------- 3xTF32 GEMM body + fused row-sumsq epilogue ----------------
#define AST 36
#define BST 72
template <int SRC>
__device__ __forceinline__ void gemm_body(const float* __restrict__ Aext,
                                          const float* __restrict__ B,
                                          float* __restrict__ ss,
                                          int M, int N, int K,
                                          int bx, int nColTiles) {
    const float* A = (SRC == 0) ? Aext : g_buf;
    __shared__ __align__(16) float AsF[2][128 * AST];
    __shared__ __align__(16) float BsF[2][32 * BST];
    const int tid = threadIdx.x;
    const int wid = tid >> 5, lane = tid & 31;
    const int g = lane >> 2, t = lane & 3;
    const int warpM = wid >> 1, warpN = wid & 1;
    const int rowBase = (bx / nColTiles) * 128, colBase = (bx % nColTiles) * 64;

    auto issue = [&](int ch, int buf) {
        const int k0 = ch * 32;
#pragma unroll
        for (int i = 0; i < 4; i++) {
            int f = tid + i * 256;
            int r = f >> 3, c4 = f & 7;
            int gr = rowBase + r, gk = k0 + c4 * 4;
            bool ok = (gr < M) && (gk < K);
            const float* src = ok ? (A + (size_t)gr * K + gk) : A;
            cp_async16(&AsF[buf][r * AST + c4 * 4], src, ok);
        }
#pragma unroll
        for (int i = 0; i < 2; i++) {
            int f = tid + i * 256;
            int r = f >> 4, c4 = f & 15;
            int gk = k0 + r, gn = colBase + c4 * 4;
            bool ok = (gk < K) && (gn < N);
            const float* src = ok ? (B + (size_t)gk * N + gn) : B;
            cp_async16(&BsF[buf][r * BST + c4 * 4], src, ok);
        }
        CP_COMMIT();
    };

    float acc[2][4][4];
#pragma unroll
    for (int mt = 0; mt < 2; mt++)
#pragma unroll
        for (int nt = 0; nt < 4; nt++)
#pragma unroll
            for (int r = 0; r < 4; r++) acc[mt][nt][r] = 0.f;

    const int nCh = (K + 31) / 32;
    issue(0, 0);
    for (int ch = 0; ch < nCh; ch++) {
        const int cur = ch & 1;
        if (ch + 1 < nCh) { issue(ch + 1, cur ^ 1); CP_WAIT(1); }
        else              { CP_WAIT(0); }
        __syncthreads();
#pragma unroll
        for (int kk = 0; kk < 4; kk++) {
            const int kl = kk * 8;
            uint32_t aH[2][4], aL[2][4];
#pragma unroll
            for (int mt = 0; mt < 2; mt++) {
                int m0 = warpM * 32 + mt * 16 + g;
                float a0 = AsF[cur][m0 * AST + kl + t];
                float a1 = AsF[cur][(m0 + 8) * AST + kl + t];
                float a2 = AsF[cur][m0 * AST + kl + t + 4];
                float a3 = AsF[cur][(m0 + 8) * AST + kl + t + 4];
                split_tf32(a0, aH[mt][0], aL[mt][0]);
                split_tf32(a1, aH[mt][1], aL[mt][1]);
                split_tf32(a2, aH[mt][2], aL[mt][2]);
                split_tf32(a3, aH[mt][3], aL[mt][3]);
            }
#pragma unroll
            for (int nt = 0; nt < 4; nt++) {
                int n0 = warpN * 32 + nt * 8 + g;
                float b0 = BsF[cur][(kl + t) * BST + n0];
                float b1 = BsF[cur][(kl + t + 4) * BST + n0];
                uint32_t bH[2], bL[2];
                split_tf32(b0, bH[0], bL[0]);
                split_tf32(b1, bH[1], bL[1]);
#pragma unroll
                for (int mt = 0; mt < 2; mt++) {
                    mma_tf32(acc[mt][nt], aH[mt], bL);
                    mma_tf32(acc[mt][nt], aL[mt], bH);
                    mma_tf32(acc[mt][nt], aH[mt], bH);
                }
            }
        }
        __syncthreads();
    }
#pragma unroll
    for (int mt = 0; mt < 2; mt++) {
#pragma unroll
        for (int half = 0; half < 2; half++) {
            int m = rowBase + warpM * 32 + mt * 16 + g + half * 8;
            float ssp = 0.f;
#pragma unroll
            for (int nt = 0; nt < 4; nt++) {
                int n = colBase + warpN * 32 + nt * 8 + t * 2;
                if (n < N && m < M) {
                    float c0 = acc[mt][nt][half * 2], c1 = acc[mt][nt][half * 2 + 1];
                    *reinterpret_cast<float2*>(g_h + (size_t)m * N + n) = make_float2(c0, c1);
                    ssp += c0 * c0 + c1 * c1;
                }
            }
            ssp += __shfl_xor_sync(0xffffffffu, ssp, 1);
            ssp += __shfl_xor_sync(0xffffffffu, ssp, 2);
            if (t == 0 && m < M) atomicAdd(&ss[m], ssp);
        }
    }
}

// ---------------- kernels ----------------
// fused: [GEMM1 (+ss1) | edge count | mask1 gen | mask2 gen]
__global__ void __launch_bounds__(256) k_gemm1_count(const float* __restrict__ x,
                                                     const float* __restrict__ W1,
                                                     const int* __restrict__ dst,
                                                     uint32_t k1a, uint32_t k1b,
                                                     uint32_t k2a, uint32_t k2b) {
    if (blockIdx.x < GEMM1_BLOCKS) {
        gemm_body<0>(x, W1, g_ss1, N_NODES, H1C, IN_CH, blockIdx.x, GEMM1_NCT);
    } else if (blockIdx.x < GEMM1_BLOCKS + COUNT_BLOCKS) {
        int e = (blockIdx.x - GEMM1_BLOCKS) * 256 + threadIdx.x;
        if (e < E_EDGES) atomicAdd(&g_deg[dst[e]], 1);
    } else if (blockIdx.x < GEMM1_BLOCKS + COUNT_BLOCKS + MASK1_BLOCKS) {
        int gwarp = (blockIdx.x - GEMM1_BLOCKS - COUNT_BLOCKS) * 8 + (threadIdx.x >> 5);
        gen_mask(g_mask1, MASK1_WORDS, gwarp, threadIdx.x & 31, k1a, k1b);
    } else {
        int gwarp = (blockIdx.x - GEMM1_BLOCKS - COUNT_BLOCKS - MASK1_BLOCKS) * 8
                    + (threadIdx.x >> 5);
        gen_mask(g_mask2, MASK2_WORDS, gwarp, threadIdx.x & 31, k2a, k2b);
    }
}

// scan1: local (per-block) exclusive prefix + block sums; also ss1 -> invn.
__global__ void k_scan1() {
    __shared__ int sh[256];
    int b = blockIdx.x, t = threadIdx.x, i = b * 256 + t;
    int v = (i < N_NODES) ? (g_deg[i] + 1) : 0;   // +1 = self-loop
    if (i < N_NODES) g_invn[i] = rsqrtf(fmaxf(g_ss1[i], 1e-24f));
    sh[t] = v;
    __syncthreads();
    for (int off = 1; off < 256; off <<= 1) {
        int x = (t >= off) ? sh[t - off] : 0;
        __syncthreads();
        sh[t] += x;
        __syncthreads();
    }
    if (i < N_NODES) g_rowptr[i] = sh[t] - v;   // local exclusive prefix
    if (t == 255) g_bsum[b] = sh[255];
}

// fused: [scan finalize + CSR fill]. Every block redundantly prefix-sums the
// 196 block sums in smem; blocks 0..195 publish the FINAL rowptr to g_rowptr2;
// all blocks scatter edges using local rowptr + smem offset (no race on g_rowptr).
__global__ void k_fill(const int* __restrict__ src, const int* __restrict__ dst) {
    __shared__ int sp[256];                     // inclusive prefix of bsum
    int t = threadIdx.x;
    sp[t] = (t < SCAN_BLOCKS) ? g_bsum[t] : 0;
    __syncthreads();
    for (int off = 1; off < 256; off <<= 1) {
        int x = (t >= off) ? sp[t - off] : 0;
        __syncthreads();
        sp[t] += x;
        __syncthreads();
    }
    int e = blockIdx.x * 256 + t;
    if (blockIdx.x < SCAN_BLOCKS) {
        if (e < N_NODES) {
            int off = (blockIdx.x == 0) ? 0 : sp[blockIdx.x - 1];
            g_rowptr2[e] = g_rowptr[e] + off;
        }
        if (e == 0) g_rowptr2[N_NODES] = E_TOT;
    }
    if (e < N_NODES) g_deg[e] = 0;              // reset for replay
    if (e >= E_TOT) return;
    int s, d;
    if (e < E_EDGES) { s = src[e]; d = dst[e]; }
    else             { s = e - E_EDGES; d = s; }
    int blk = d >> 8;
    int off = (blk == 0) ? 0 : sp[blk - 1];
    int pos = atomicAdd(&g_cursor[d], 1);
    g_csrsrc[g_rowptr[d] + off + pos] = s;
}

__global__ void __launch_bounds__(256) k_gemm2(const float* __restrict__ W2) {
    gemm_body<1>(nullptr, W2, g_ss2, N_NODES, H2C, H1C, blockIdx.x, GEMM2_NCT);
}

// ---------------- fused attention + softmax + agg + relu + dropout ----------
// One warp per dst node; float4 row loads; unroll-2; mask-based dropout.
template <int D, bool USE_INV, bool RESET1>
__global__ void __launch_bounds__(128) k_node(const float* __restrict__ beta_p) {
    const uint32_t* mask = USE_INV ? g_mask1 : g_mask2;
    int v = (blockIdx.x * blockDim.x + threadIdx.x) >> 5;
    int lane = threadIdx.x & 31;
    if (v >= N_NODES) return;
    constexpr int C4 = (D + 127) / 128;
    const float4 z4 = make_float4(0.f, 0.f, 0.f, 0.f);

    float4 hv[C4];
    int vbase = v * D;
#pragma unroll
    for (int c = 0; c < C4; c++) {
        int f0 = (c * 32 + lane) * 4;
        hv[c] = (f0 < D) ? *reinterpret_cast<const float4*>(g_h + vbase + f0) : z4;
    }
    float nvv = USE_INV ? g_invn[v] : rsqrtf(fmaxf(g_ss2[v], 1e-24f));
    float bi = __ldg(beta_p) * nvv;
    if (RESET1 && lane == 0) { g_cursor[v] = 0; g_ss1[v] = 0.f; }
    int e0 = g_rowptr2[v], e1 = g_rowptr2[v + 1];
    float denom = 0.0f;
    float4 acc[C4];
#pragma unroll
    for (int c = 0; c < C4; c++) acc[c] = z4;

    for (int e = e0; e < e1; e += 2) {
        bool hasB = (e + 1 < e1);
        int sA = g_csrsrc[e];
        int sB = hasB ? g_csrsrc[e + 1] : sA;
        float nA = USE_INV ? g_invn[sA] : rsqrtf(fmaxf(g_ss2[sA], 1e-24f));
        float nB = USE_INV ? g_invn[sB] : rsqrtf(fmaxf(g_ss2[sB], 1e-24f));
        int aBase = sA * D, bBase = sB * D;
        float4 hA[C4], hB[C4];
#pragma unroll
        for (int c = 0; c < C4; c++) {
            int f0 = (c * 32 + lane) * 4;
            bool ok = (f0 < D);
            hA[c] = ok ? *reinterpret_cast<const float4*>(g_h + aBase + f0) : z4;
            hB[c] = ok ? *reinterpret_cast<const float4*>(g_h + bBase + f0) : z4;
        }
        float dA = 0.f, dB = 0.f;
#pragma unroll
        for (int c = 0; c < C4; c++) {
            dA += hv[c].x * hA[c].x + hv[c].y * hA[c].y + hv[c].z * hA[c].z + hv[c].w * hA[c].w;
            dB += hv[c].x * hB[c].x + hv[c].y * hB[c].y + hv[c].z * hB[c].z + hv[c].w * hB[c].w;
        }
#pragma unroll
        for (int o = 16; o; o >>= 1) {
            dA += __shfl_xor_sync(0xffffffffu, dA, o);
            dB += __shfl_xor_sync(0xffffffffu, dB, o);
        }
        float wA = __expf(bi * dA * nA);
        float wB = hasB ? __expf(bi * dB * nB) : 0.0f;
        denom += wA + wB;
#pragma unroll
        for (int c = 0; c < C4; c++) {
            acc[c].x += wA * hA[c].x + wB * hB[c].x;
            acc[c].y += wA * hA[c].y + wB * hB[c].y;
            acc[c].z += wA * hA[c].z + wB * hB[c].z;
            acc[c].w += wA * hA[c].w + wB * hB[c].w;
        }
    }
    float dinv = 1.0f / fmaxf(denom, 1e-12f);
#pragma unroll
    for (int c = 0; c < C4; c++) {
        int f0 = (c * 32 + lane) * 4;
        if (f0 >= D) continue;
        uint32_t idx4 = (uint32_t)(vbase + f0);
        uint32_t word = mask[idx4 >> 5];
        uint32_t sh = idx4 & 31u;
        float vals[4] = {acc[c].x * dinv, acc[c].y * dinv, acc[c].z * dinv, acc[c].w * dinv};
        float4 o4;
        float* op = reinterpret_cast<float*>(&o4);
#pragma unroll
        for (int comp = 0; comp < 4; comp++) {
            float val = fmaxf(vals[comp], 0.0f);
            bool keep = (word >> (sh + comp)) & 1u;
            op[comp] = keep ? (val / 0.9f) : 0.0f;
        }
        *reinterpret_cast<float4*>(g_buf + vbase + f0) = o4;
    }
}

// ---------------- layer 3 dedicated path (D=2) ----------------
__global__ void k_gemm3_norm(const float* __restrict__ W3) {
    int v = (blockIdx.x * blockDim.x + threadIdx.x) >> 5;
    int lane = threadIdx.x & 31;
    if (v >= N_NODES) return;
    if (lane == 0) g_ss2[v] = 0.f;   // reset for replay
    float s0 = 0.f, s1 = 0.f;
#pragma unroll
    for (int j = 0; j < 4; j++) {
        int d = lane + 32 * j;
        if (d < H2C) {
            float hval = g_buf[v * H2C + d];
            s0 += hval * __ldg(W3 + d * 2 + 0);
            s1 += hval * __ldg(W3 + d * 2 + 1);
        }
    }
#pragma unroll
    for (int o = 16; o; o >>= 1) {
        s0 += __shfl_xor_sync(0xffffffffu, s0, o);
        s1 += __shfl_xor_sync(0xffffffffu, s1, o);
    }
    if (lane == 0) {
        g_h[v * 2 + 0] = s0;
        g_h[v * 2 + 1] = s1;
        g_invn[v] = 1.0f / fmaxf(sqrtf(s0 * s0 + s1 * s1), 1e-12f);
    }
}

__global__ void k_node3(const float* __restrict__ beta_p, float* __restrict__ out) {
    int v = blockIdx.x * blockDim.x + threadIdx.x;
    if (v >= N_NODES) return;
    const float2* h2 = reinterpret_cast<const float2*>(g_h);
    float2 hv = h2[v];
    float bi = __ldg(beta_p) * g_invn[v];
    int e0 = g_rowptr2[v], e1 = g_rowptr2[v + 1];
    float denom = 0.f, a0 = 0.f, a1 = 0.f;
    for (int e = e0; e < e1; e++) {
        int s = g_csrsrc[e];
        float2 hs = h2[s];
        float w = __expf(bi * (hv.x * hs.x + hv.y * hs.y) * g_invn[s]);
        denom += w;
        a0 += w * hs.x;
        a1 += w * hs.y;
    }
    float dinv = 1.0f / fmaxf(denom, 1e-12f);
    out[v * 2 + 0] = fmaxf(a0 * dinv, 0.f);
    out[v * 2 + 1] = fmaxf(a1 * dinv, 0.f);
}

extern "C" void kernel_launch(void* const* d_in, const int* in_sizes, int n_in,
                              void* d_out, int out_size) {
    const float* x  = (const float*)d_in[0];
    const int*   ei = (const int*)d_in[1];
    const float* W1 = (const float*)d_in[2];
    const float* W2 = (const float*)d_in[3];
    const float* W3 = (const float*)d_in[4];
    const float* b1 = (const float*)d_in[5];
    const float* b2 = (const float*)d_in[6];
    const float* b3 = (const float*)d_in[7];
    float* out = (float*)d_out;
    const int* src = ei;
    const int* dst = ei + E_EDGES;

    uint32_t k1a, k1b, k2a, k2b;
    threefry2x32(0u, 42u, 0u, 0u, k1a, k1b);
    threefry2x32(0u, 42u, 0u, 1u, k2a, k2b);

    k_gemm1_count<<<GEMM1_BLOCKS + COUNT_BLOCKS + MASK1_BLOCKS + MASK2_BLOCKS, 256>>>(
        x, W1, dst, k1a, k1b, k2a, k2b);                                // 1
    k_scan1<<<SCAN_BLOCKS, 256>>>();                                    // 2
    k_fill<<<FILL_BLOCKS, 256>>>(src, dst);                             // 3
    k_node<H1C, true, true><<<NODE_BLOCKS, 128>>>(b1);                  // 4 <- profiled
    k_gemm2<<<GEMM2_BLOCKS, 256>>>(W2);                                 // 5
    k_node<H2C, false, false><<<NODE_BLOCKS, 128>>>(b2);                // 6
    k_gemm3_norm<<<WNODE_BLOCKS, 256>>>(W3);                            // 7
    k_node3<<<SCAN_BLOCKS, 256>>>(b3, out);                             // 8
    (void)in_sizes; (void)n_in; (void)out_size;
}

// round 15
// speedup vs baseline: 1.0446x; 1.0276x over previous
#include <cuda_runtime.h>
#include <math.h>
#include <stdint.h>

#define N_NODES 50000
#define E_EDGES 800000
#define E_TOT   (E_EDGES + N_NODES)
#define IN_CH 128
#define H1C 200
#define H2C 100
#define OUTC 2

#define GEMM1_NCT    4
#define GEMM1_NRT    391
#define GEMM1_BLOCKS (GEMM1_NCT * GEMM1_NRT)
#define COUNT_BLOCKS 3125
#define GEMM2_NCT    2
#define GEMM2_BLOCKS (GEMM2_NCT * GEMM1_NRT)
#define FILL_BLOCKS  3321
#define NODE_BLOCKS  12500                  // 50000 warps / 4 (128-thread blocks)
#define WNODE_BLOCKS 6250                   // 50000 warps / 8 (256-thread blocks)
#define SCAN_BLOCKS  196

#define MASK1_WORDS  (N_NODES * H1C / 32)   // 312500
#define MASK2_WORDS  (N_NODES * H2C / 32)   // 156250
#define MASK1_BLOCKS ((MASK1_WORDS + 255) / 256)  // 1221
#define MASK2_BLOCKS ((MASK2_WORDS + 255) / 256)  // 611

// ---------------- scratch (static __device__, zero-initialized) ----------------
__device__ float g_h[(size_t)N_NODES * H1C];
__device__ float g_buf[(size_t)N_NODES * H1C];
__device__ float g_ss1[N_NODES];            // reset by k_node1
__device__ float g_ss2[N_NODES];            // reset by k_gemm3_norm
__device__ float g_invn[N_NODES];           // layer-1 invn (scan1), then layer-3
__device__ int   g_deg[N_NODES];            // reset by k_fill
__device__ int   g_rowptr[N_NODES];         // LOCAL (per-block) prefix, from scan1
__device__ int   g_rowptr2[N_NODES + 1];    // FINAL rowptr, from k_fill
__device__ int   g_cursor[N_NODES];         // reset by k_node1
__device__ int   g_csrsrc[E_TOT];
__device__ int   g_bsum[256];               // overwritten by scan1 each run
__device__ uint32_t g_mask1[MASK1_WORDS];   // overwritten each run
__device__ uint32_t g_mask2[MASK2_WORDS];   // overwritten each run

// ---------------- Threefry-2x32 (matches JAX, confirmed) ----------------
__host__ __device__ inline uint32_t rotl32(uint32_t v, int d) {
    return (v << d) | (v >> (32 - d));
}
__host__ __device__ inline void threefry2x32(uint32_t key0, uint32_t key1,
                                             uint32_t x0, uint32_t x1,
                                             uint32_t& o0, uint32_t& o1) {
    uint32_t ks[3] = {key0, key1, key0 ^ key1 ^ 0x1BD11BDAu};
    const int rot[8] = {13, 15, 26, 6, 17, 29, 16, 24};
    x0 += ks[0]; x1 += ks[1];
#pragma unroll
    for (int i = 0; i < 5; i++) {
        const int* r = &rot[(i & 1) * 4];
#pragma unroll
        for (int j = 0; j < 4; j++) { x0 += x1; x1 = rotl32(x1, r[j]); x1 ^= x0; }
        x0 += ks[(i + 1) % 3];
        x1 += ks[(i + 2) % 3] + (uint32_t)(i + 1);
    }
    o0 = x0; o1 = x1;
}

// Warp-cooperative dropout-mask generation (semantics confirmed in R13/R14).
__device__ __forceinline__ void gen_mask(uint32_t* mask, int nwords, int gwarp,
                                         int lane, uint32_t k0, uint32_t k1) {
    int base = gwarp * 32;
    if (base >= nwords) return;
    uint32_t myword = 0;
#pragma unroll 4
    for (int k = 0; k < 32; k++) {
        uint32_t idx = (uint32_t)(base + k) * 32u + (uint32_t)lane;
        uint32_t o0, o1;
        threefry2x32(k0, k1, 0u, idx, o0, o1);
        uint32_t bits = o0 ^ o1;
        float u = __uint_as_float((bits >> 9) | 0x3f800000u) - 1.0f;
        uint32_t b = __ballot_sync(0xffffffffu, u < 0.9f);
        if (lane == k) myword = b;
    }
    if (base + lane < nwords) mask[base + lane] = myword;
}

// ---------------- cp.async helpers ----------------
__device__ __forceinline__ void cp_async16(void* smem_dst, const void* gsrc, bool valid) {
    uint32_t saddr = (uint32_t)__cvta_generic_to_shared(smem_dst);
    int bytes = valid ? 16 : 0;
    asm volatile("cp.async.cg.shared.global [%0], [%1], 16, %2;\n"
                 :: "r"(saddr), "l"(gsrc), "r"(bytes));
}
#define CP_COMMIT()  asm volatile("cp.async.commit_group;\n")
#define CP_WAIT(n)   asm volatile("cp.async.wait_group %0;\n" :: "n"(n))

// ---------------- tf32 helpers ----------------
__device__ __forceinline__ uint32_t f2tf32(float f) {
    uint32_t o;
    asm volatile("cvt.rna.tf32.f32 %0, %1;" : "=r"(o) : "f"(f));
    return o;
}
__device__ __forceinline__ void split_tf32(float f, uint32_t& hi, uint32_t& lo) {
    hi = f2tf32(f);
    lo = f2tf32(f - __uint_as_float(hi));
}
__device__ __forceinline__ void mma_tf32(float* c, const uint32_t* a, const uint32_t* b) {
    asm volatile(
        "mma.sync.aligned.m16n8k8.row.col.f32.tf32.tf32.f32 "
        "{%0,%1,%2,%3}, {%4,%5,%6,%7}, {%8,%9}, {%0,%1,%2,%3};\n"
        : "+f"(c[0]), "+f"(c[1]), "+f"(c[2]), "+f"(c[3])
        : "r"(a[0]), "r"(a[1]), "r"(a[2]), "r"(a[3]), "r"(b[0]), "r"(b[1]));
}

// ---------------- 3xTF32 GEMM body + fused row-sumsq epilogue ----------------
#define AST 36
#define BST 72
template <int SRC>
__device__ __forceinline__ void gemm_body(const float* __restrict__ Aext,
                                          const float* __restrict__ B,
                                          float* __restrict__ ss,
                                          int M, int N, int K,
                                          int bx, int nColTiles) {
    const float* A = (SRC == 0) ? Aext : g_buf;
    __shared__ __align__(16) float AsF[2][128 * AST];
    __shared__ __align__(16) float BsF[2][32 * BST];
    const int tid = threadIdx.x;
    const int wid = tid >> 5, lane = tid & 31;
    const int g = lane >> 2, t = lane & 3;
    const int warpM = wid >> 1, warpN = wid & 1;
    const int rowBase = (bx / nColTiles) * 128, colBase = (bx % nColTiles) * 64;

    auto issue = [&](int ch, int buf) {
        const int k0 = ch * 32;
#pragma unroll
        for (int i = 0; i < 4; i++) {
            int f = tid + i * 256;
            int r = f >> 3, c4 = f & 7;
            int gr = rowBase + r, gk = k0 + c4 * 4;
            bool ok = (gr < M) && (gk < K);
            const float* src = ok ? (A + (size_t)gr * K + gk) : A;
            cp_async16(&AsF[buf][r * AST + c4 * 4], src, ok);
        }
#pragma unroll
        for (int i = 0; i < 2; i++) {
            int f = tid + i * 256;
            int r = f >> 4, c4 = f & 15;
            int gk = k0 + r, gn = colBase + c4 * 4;
            bool ok = (gk < K) && (gn < N);
            const float* src = ok ? (B + (size_t)gk * N + gn) : B;
            cp_async16(&BsF[buf][r * BST + c4 * 4], src, ok);
        }
        CP_COMMIT();
    };

    float acc[2][4][4];
#pragma unroll
    for (int mt = 0; mt < 2; mt++)
#pragma unroll
        for (int nt = 0; nt < 4; nt++)
#pragma unroll
            for (int r = 0; r < 4; r++) acc[mt][nt][r] = 0.f;

    const int nCh = (K + 31) / 32;
    issue(0, 0);
    for (int ch = 0; ch < nCh; ch++) {
        const int cur = ch & 1;
        if (ch + 1 < nCh) { issue(ch + 1, cur ^ 1); CP_WAIT(1); }
        else              { CP_WAIT(0); }
        __syncthreads();
#pragma unroll
        for (int kk = 0; kk < 4; kk++) {
            const int kl = kk * 8;
            uint32_t aH[2][4], aL[2][4];
#pragma unroll
            for (int mt = 0; mt < 2; mt++) {
                int m0 = warpM * 32 + mt * 16 + g;
                float a0 = AsF[cur][m0 * AST + kl + t];
                float a1 = AsF[cur][(m0 + 8) * AST + kl + t];
                float a2 = AsF[cur][m0 * AST + kl + t + 4];
                float a3 = AsF[cur][(m0 + 8) * AST + kl + t + 4];
                split_tf32(a0, aH[mt][0], aL[mt][0]);
                split_tf32(a1, aH[mt][1], aL[mt][1]);
                split_tf32(a2, aH[mt][2], aL[mt][2]);
                split_tf32(a3, aH[mt][3], aL[mt][3]);
            }
#pragma unroll
            for (int nt = 0; nt < 4; nt++) {
                int n0 = warpN * 32 + nt * 8 + g;
                float b0 = BsF[cur][(kl + t) * BST + n0];
                float b1 = BsF[cur][(kl + t + 4) * BST + n0];
                uint32_t bH[2], bL[2];
                split_tf32(b0, bH[0], bL[0]);
                split_tf32(b1, bH[1], bL[1]);
#pragma unroll
                for (int mt = 0; mt < 2; mt++) {
                    mma_tf32(acc[mt][nt], aH[mt], bL);
                    mma_tf32(acc[mt][nt], aL[mt], bH);
                    mma_tf32(acc[mt][nt], aH[mt], bH);
                }
            }
        }
        __syncthreads();
    }
#pragma unroll
    for (int mt = 0; mt < 2; mt++) {
#pragma unroll
        for (int half = 0; half < 2; half++) {
            int m = rowBase + warpM * 32 + mt * 16 + g + half * 8;
            float ssp = 0.f;
#pragma unroll
            for (int nt = 0; nt < 4; nt++) {
                int n = colBase + warpN * 32 + nt * 8 + t * 2;
                if (n < N && m < M) {
                    float c0 = acc[mt][nt][half * 2], c1 = acc[mt][nt][half * 2 + 1];
                    *reinterpret_cast<float2*>(g_h + (size_t)m * N + n) = make_float2(c0, c1);
                    ssp += c0 * c0 + c1 * c1;
                }
            }
            ssp += __shfl_xor_sync(0xffffffffu, ssp, 1);
            ssp += __shfl_xor_sync(0xffffffffu, ssp, 2);
            if (t == 0 && m < M) atomicAdd(&ss[m], ssp);
        }
    }
}

// ---------------- kernels ----------------
// fused: [GEMM1 (+ss1) | mask1 gen | edge count]
// mask1 blocks placed BEFORE count so they co-schedule with long GEMM blocks;
// latency-tolerant atomic count forms the tail.
__global__ void __launch_bounds__(256) k_gemm1_count(const float* __restrict__ x,
                                                     const float* __restrict__ W1,
                                                     const int* __restrict__ dst,
                                                     uint32_t k1a, uint32_t k1b) {
    if (blockIdx.x < GEMM1_BLOCKS) {
        gemm_body<0>(x, W1, g_ss1, N_NODES, H1C, IN_CH, blockIdx.x, GEMM1_NCT);
    } else if (blockIdx.x < GEMM1_BLOCKS + MASK1_BLOCKS) {
        int gwarp = (blockIdx.x - GEMM1_BLOCKS) * 8 + (threadIdx.x >> 5);
        gen_mask(g_mask1, MASK1_WORDS, gwarp, threadIdx.x & 31, k1a, k1b);
    } else {
        int e = (blockIdx.x - GEMM1_BLOCKS - MASK1_BLOCKS) * 256 + threadIdx.x;
        if (e < E_EDGES) atomicAdd(&g_deg[dst[e]], 1);
    }
}

// scan1: local (per-block) exclusive prefix + block sums; also ss1 -> invn.
__global__ void k_scan1() {
    __shared__ int sh[256];
    int b = blockIdx.x, t = threadIdx.x, i = b * 256 + t;
    int v = (i < N_NODES) ? (g_deg[i] + 1) : 0;   // +1 = self-loop
    if (i < N_NODES) g_invn[i] = rsqrtf(fmaxf(g_ss1[i], 1e-24f));
    sh[t] = v;
    __syncthreads();
    for (int off = 1; off < 256; off <<= 1) {
        int x = (t >= off) ? sh[t - off] : 0;
        __syncthreads();
        sh[t] += x;
        __syncthreads();
    }
    if (i < N_NODES) g_rowptr[i] = sh[t] - v;   // local exclusive prefix
    if (t == 255) g_bsum[b] = sh[255];
}

// fused: [scan finalize + CSR fill]. Every block redundantly prefix-sums the
// 196 block sums in smem; blocks 0..195 publish the FINAL rowptr to g_rowptr2;
// all blocks scatter edges using local rowptr + smem offset.
__global__ void k_fill(const int* __restrict__ src, const int* __restrict__ dst) {
    __shared__ int sp[256];                     // inclusive prefix of bsum
    int t = threadIdx.x;
    sp[t] = (t < SCAN_BLOCKS) ? g_bsum[t] : 0;
    __syncthreads();
    for (int off = 1; off < 256; off <<= 1) {
        int x = (t >= off) ? sp[t - off] : 0;
        __syncthreads();
        sp[t] += x;
        __syncthreads();
    }
    int e = blockIdx.x * 256 + t;
    if (blockIdx.x < SCAN_BLOCKS) {
        if (e < N_NODES) {
            int off = (blockIdx.x == 0) ? 0 : sp[blockIdx.x - 1];
            g_rowptr2[e] = g_rowptr[e] + off;
        }
        if (e == 0) g_rowptr2[N_NODES] = E_TOT;
    }
    if (e < N_NODES) g_deg[e] = 0;              // reset for replay
    if (e >= E_TOT) return;
    int s, d;
    if (e < E_EDGES) { s = src[e]; d = dst[e]; }
    else             { s = e - E_EDGES; d = s; }
    int blk = d >> 8;
    int off = (blk == 0) ? 0 : sp[blk - 1];
    int pos = atomicAdd(&g_cursor[d], 1);
    g_csrsrc[g_rowptr[d] + off + pos] = s;
}

// fused: [GEMM2 (+ss2) | mask2 gen] — mask2 hides in gemm2's issue slack;
// mask2 is first consumed by k_node2 (next launch).
__global__ void __launch_bounds__(256) k_gemm2(const float* __restrict__ W2,
                                               uint32_t k2a, uint32_t k2b) {
    if (blockIdx.x < GEMM2_BLOCKS) {
        gemm_body<1>(nullptr, W2, g_ss2, N_NODES, H2C, H1C, blockIdx.x, GEMM2_NCT);
    } else {
        int gwarp = (blockIdx.x - GEMM2_BLOCKS) * 8 + (threadIdx.x >> 5);
        gen_mask(g_mask2, MASK2_WORDS, gwarp, threadIdx.x & 31, k2a, k2b);
    }
}

// ---------------- fused attention + softmax + agg + relu + dropout ----------
// One warp per dst node; float4 row loads; unroll-2; mask-based dropout.
template <int D, bool USE_INV, bool RESET1>
__global__ void __launch_bounds__(128) k_node(const float* __restrict__ beta_p) {
    const uint32_t* mask = USE_INV ? g_mask1 : g_mask2;
    int v = (blockIdx.x * blockDim.x + threadIdx.x) >> 5;
    int lane = threadIdx.x & 31;
    if (v >= N_NODES) return;
    constexpr int C4 = (D + 127) / 128;
    const float4 z4 = make_float4(0.f, 0.f, 0.f, 0.f);

    float4 hv[C4];
    int vbase = v * D;
#pragma unroll
    for (int c = 0; c < C4; c++) {
        int f0 = (c * 32 + lane) * 4;
        hv[c] = (f0 < D) ? *reinterpret_cast<const float4*>(g_h + vbase + f0) : z4;
    }
    float nvv = USE_INV ? g_invn[v] : rsqrtf(fmaxf(g_ss2[v], 1e-24f));
    float bi = __ldg(beta_p) * nvv;
    if (RESET1 && lane == 0) { g_cursor[v] = 0; g_ss1[v] = 0.f; }
    int e0 = g_rowptr2[v], e1 = g_rowptr2[v + 1];
    float denom = 0.0f;
    float4 acc[C4];
#pragma unroll
    for (int c = 0; c < C4; c++) acc[c] = z4;

    for (int e = e0; e < e1; e += 2) {
        bool hasB = (e + 1 < e1);
        int sA = g_csrsrc[e];
        int sB = hasB ? g_csrsrc[e + 1] : sA;
        float nA = USE_INV ? g_invn[sA] : rsqrtf(fmaxf(g_ss2[sA], 1e-24f));
        float nB = USE_INV ? g_invn[sB] : rsqrtf(fmaxf(g_ss2[sB], 1e-24f));
        int aBase = sA * D, bBase = sB * D;
        float4 hA[C4], hB[C4];
#pragma unroll
        for (int c = 0; c < C4; c++) {
            int f0 = (c * 32 + lane) * 4;
            bool ok = (f0 < D);
            hA[c] = ok ? *reinterpret_cast<const float4*>(g_h + aBase + f0) : z4;
            hB[c] = ok ? *reinterpret_cast<const float4*>(g_h + bBase + f0) : z4;
        }
        float dA = 0.f, dB = 0.f;
#pragma unroll
        for (int c = 0; c < C4; c++) {
            dA += hv[c].x * hA[c].x + hv[c].y * hA[c].y + hv[c].z * hA[c].z + hv[c].w * hA[c].w;
            dB += hv[c].x * hB[c].x + hv[c].y * hB[c].y + hv[c].z * hB[c].z + hv[c].w * hB[c].w;
        }
#pragma unroll
        for (int o = 16; o; o >>= 1) {
            dA += __shfl_xor_sync(0xffffffffu, dA, o);
            dB += __shfl_xor_sync(0xffffffffu, dB, o);
        }
        float wA = __expf(bi * dA * nA);
        float wB = hasB ? __expf(bi * dB * nB) : 0.0f;
        denom += wA + wB;
#pragma unroll
        for (int c = 0; c < C4; c++) {
            acc[c].x += wA * hA[c].x + wB * hB[c].x;
            acc[c].y += wA * hA[c].y + wB * hB[c].y;
            acc[c].z += wA * hA[c].z + wB * hB[c].z;
            acc[c].w += wA * hA[c].w + wB * hB[c].w;
        }
    }
    float dinv = 1.0f / fmaxf(denom, 1e-12f);
#pragma unroll
    for (int c = 0; c < C4; c++) {
        int f0 = (c * 32 + lane) * 4;
        if (f0 >= D) continue;
        uint32_t idx4 = (uint32_t)(vbase + f0);
        uint32_t word = mask[idx4 >> 5];
        uint32_t sh = idx4 & 31u;
        float vals[4] = {acc[c].x * dinv, acc[c].y * dinv, acc[c].z * dinv, acc[c].w * dinv};
        float4 o4;
        float* op = reinterpret_cast<float*>(&o4);
#pragma unroll
        for (int comp = 0; comp < 4; comp++) {
            float val = fmaxf(vals[comp], 0.0f);
            bool keep = (word >> (sh + comp)) & 1u;
            op[comp] = keep ? (val / 0.9f) : 0.0f;
        }
        *reinterpret_cast<float4*>(g_buf + vbase + f0) = o4;
    }
}

// ---------------- layer 3 dedicated path (D=2) ----------------
__global__ void k_gemm3_norm(const float* __restrict__ W3) {
    int v = (blockIdx.x * blockDim.x + threadIdx.x) >> 5;
    int lane = threadIdx.x & 31;
    if (v >= N_NODES) return;
    if (lane == 0) g_ss2[v] = 0.f;   // reset for replay
    float s0 = 0.f, s1 = 0.f;
#pragma unroll
    for (int j = 0; j < 4; j++) {
        int d = lane + 32 * j;
        if (d < H2C) {
            float hval = g_buf[v * H2C + d];
            s0 += hval * __ldg(W3 + d * 2 + 0);
            s1 += hval * __ldg(W3 + d * 2 + 1);
        }
    }
#pragma unroll
    for (int o = 16; o; o >>= 1) {
        s0 += __shfl_xor_sync(0xffffffffu, s0, o);
        s1 += __shfl_xor_sync(0xffffffffu, s1, o);
    }
    if (lane == 0) {
        g_h[v * 2 + 0] = s0;
        g_h[v * 2 + 1] = s1;
        g_invn[v] = 1.0f / fmaxf(sqrtf(s0 * s0 + s1 * s1), 1e-12f);
    }
}

__global__ void k_node3(const float* __restrict__ beta_p, float* __restrict__ out) {
    int v = blockIdx.x * blockDim.x + threadIdx.x;
    if (v >= N_NODES) return;
    const float2* h2 = reinterpret_cast<const float2*>(g_h);
    float2 hv = h2[v];
    float bi = __ldg(beta_p) * g_invn[v];
    int e0 = g_rowptr2[v], e1 = g_rowptr2[v + 1];
    float denom = 0.f, a0 = 0.f, a1 = 0.f;
    for (int e = e0; e < e1; e++) {
        int s = g_csrsrc[e];
        float2 hs = h2[s];
        float w = __expf(bi * (hv.x * hs.x + hv.y * hs.y) * g_invn[s]);
        denom += w;
        a0 += w * hs.x;
        a1 += w * hs.y;
    }
    float dinv = 1.0f / fmaxf(denom, 1e-12f);
    out[v * 2 + 0] = fmaxf(a0 * dinv, 0.f);
    out[v * 2 + 1] = fmaxf(a1 * dinv, 0.f);
}

extern "C" void kernel_launch(void* const* d_in, const int* in_sizes, int n_in,
                              void* d_out, int out_size) {
    const float* x  = (const float*)d_in[0];
    const int*   ei = (const int*)d_in[1];
    const float* W1 = (const float*)d_in[2];
    const float* W2 = (const float*)d_in[3];
    const float* W3 = (const float*)d_in[4];
    const float* b1 = (const float*)d_in[5];
    const float* b2 = (const float*)d_in[6];
    const float* b3 = (const float*)d_in[7];
    float* out = (float*)d_out;
    const int* src = ei;
    const int* dst = ei + E_EDGES;

    uint32_t k1a, k1b, k2a, k2b;
    threefry2x32(0u, 42u, 0u, 0u, k1a, k1b);
    threefry2x32(0u, 42u, 0u, 1u, k2a, k2b);

    k_gemm1_count<<<GEMM1_BLOCKS + MASK1_BLOCKS + COUNT_BLOCKS, 256>>>(
        x, W1, dst, k1a, k1b);                                          // 1
    k_scan1<<<SCAN_BLOCKS, 256>>>();                                    // 2
    k_fill<<<FILL_BLOCKS, 256>>>(src, dst);                             // 3
    k_node<H1C, true, true><<<NODE_BLOCKS, 128>>>(b1);                  // 4 <- profiled
    k_gemm2<<<GEMM2_BLOCKS + MASK2_BLOCKS, 256>>>(W2, k2a, k2b);        // 5
    k_node<H2C, false, false><<<NODE_BLOCKS, 128>>>(b2);                // 6
    k_gemm3_norm<<<WNODE_BLOCKS, 256>>>(W3);                            // 7
    k_node3<<<SCAN_BLOCKS, 256>>>(b3, out);                             // 8
    (void)in_sizes; (void)n_in; (void)out_size;
}

// round 16
// speedup vs baseline: 1.0473x; 1.0026x over previous
#include <cuda_runtime.h>
#include <math.h>
#include <stdint.h>

#define N_NODES 50000
#define E_EDGES 800000
#define E_TOT   (E_EDGES + N_NODES)
#define IN_CH 128
#define H1C 200
#define H2C 100
#define OUTC 2

#define GEMM1_NCT    4
#define GEMM1_NRT    391
#define GEMM1_BLOCKS (GEMM1_NCT * GEMM1_NRT)
#define COUNT_BLOCKS 3125
#define GEMM2_NCT    2
#define GEMM2_BLOCKS (GEMM2_NCT * GEMM1_NRT)
#define FILL_BLOCKS  3321
#define NODE_BLOCKS  12500                  // 50000 warps / 4 (128-thread blocks)
#define WNODE_BLOCKS 6250
#define SCAN_BLOCKS  196

#define MASK1_WORDS  (N_NODES * H1C / 32)   // 312500
#define MASK2_WORDS  (N_NODES * H2C / 32)   // 156250
#define MASK1_BLOCKS ((MASK1_WORDS + 255) / 256)  // 1221
#define MASK2_BLOCKS ((MASK2_WORDS + 255) / 256)  // 611

// ---------------- scratch (static __device__, zero-initialized) ----------------
__device__ float g_h[(size_t)N_NODES * H1C];
__device__ float g_buf[(size_t)N_NODES * H1C];
__device__ float g_ss1[N_NODES];            // reset by k_node1
__device__ float g_ss2[N_NODES];            // reset by k_gemm3_norm
__device__ float g_invn[N_NODES];           // layer-1 invn (scan1), then layer-3
__device__ int   g_deg[N_NODES];            // reset by k_fill
__device__ int   g_rowptr[N_NODES];         // LOCAL (per-block) prefix, from scan1
__device__ int   g_rowptr2[N_NODES + 1];    // FINAL rowptr, from k_fill
__device__ int   g_cursor[N_NODES];         // reset by k_node1
__device__ int   g_csrsrc[E_TOT];
__device__ int   g_bsum[256];               // overwritten by scan1 each run
__device__ uint32_t g_mask1[MASK1_WORDS];
__device__ uint32_t g_mask2[MASK2_WORDS];

// ---------------- Threefry-2x32 (matches JAX, confirmed) ----------------
__host__ __device__ inline uint32_t rotl32(uint32_t v, int d) {
    return (v << d) | (v >> (32 - d));
}
__host__ __device__ inline void threefry2x32(uint32_t key0, uint32_t key1,
                                             uint32_t x0, uint32_t x1,
                                             uint32_t& o0, uint32_t& o1) {
    uint32_t ks[3] = {key0, key1, key0 ^ key1 ^ 0x1BD11BDAu};
    const int rot[8] = {13, 15, 26, 6, 17, 29, 16, 24};
    x0 += ks[0]; x1 += ks[1];
#pragma unroll
    for (int i = 0; i < 5; i++) {
        const int* r = &rot[(i & 1) * 4];
#pragma unroll
        for (int j = 0; j < 4; j++) { x0 += x1; x1 = rotl32(x1, r[j]); x1 ^= x0; }
        x0 += ks[(i + 1) % 3];
        x1 += ks[(i + 2) % 3] + (uint32_t)(i + 1);
    }
    o0 = x0; o1 = x1;
}

// Warp-cooperative dropout-mask generation (confirmed R13-R15).
__device__ __forceinline__ void gen_mask(uint32_t* mask, int nwords, int gwarp,
                                         int lane, uint32_t k0, uint32_t k1) {
    int base = gwarp * 32;
    if (base >= nwords) return;
    uint32_t myword = 0;
#pragma unroll 4
    for (int k = 0; k < 32; k++) {
        uint32_t idx = (uint32_t)(base + k) * 32u + (uint32_t)lane;
        uint32_t o0, o1;
        threefry2x32(k0, k1, 0u, idx, o0, o1);
        uint32_t bits = o0 ^ o1;
        float u = __uint_as_float((bits >> 9) | 0x3f800000u) - 1.0f;
        uint32_t b = __ballot_sync(0xffffffffu, u < 0.9f);
        if (lane == k) myword = b;
    }
    if (base + lane < nwords) mask[base + lane] = myword;
}

// ---------------- cp.async helpers ----------------
__device__ __forceinline__ void cp_async16(void* smem_dst, const void* gsrc, bool valid) {
    uint32_t saddr = (uint32_t)__cvta_generic_to_shared(smem_dst);
    int bytes = valid ? 16 : 0;
    asm volatile("cp.async.cg.shared.global [%0], [%1], 16, %2;\n"
                 :: "r"(saddr), "l"(gsrc), "r"(bytes));
}
#define CP_COMMIT()  asm volatile("cp.async.commit_group;\n")
#define CP_WAIT(n)   asm volatile("cp.async.wait_group %0;\n" :: "n"(n))

// ---------------- tf32 helpers ----------------
__device__ __forceinline__ uint32_t f2tf32(float f) {
    uint32_t o;
    asm volatile("cvt.rna.tf32.f32 %0, %1;" : "=r"(o) : "f"(f));
    return o;
}
__device__ __forceinline__ void split_tf32(float f, uint32_t& hi, uint32_t& lo) {
    hi = f2tf32(f);
    lo = f2tf32(f - __uint_as_float(hi));
}
__device__ __forceinline__ void mma_tf32(float* c, const uint32_t* a, const uint32_t* b) {
    asm volatile(
        "mma.sync.aligned.m16n8k8.row.col.f32.tf32.tf32.f32 "
        "{%0,%1,%2,%3}, {%4,%5,%6,%7}, {%8,%9}, {%0,%1,%2,%3};\n"
        : "+f"(c[0]), "+f"(c[1]), "+f"(c[2]), "+f"(c[3])
        : "r"(a[0]), "r"(a[1]), "r"(a[2]), "r"(a[3]), "r"(b[0]), "r"(b[1]));
}

// ---------------- 3xTF32 GEMM body + fused row-sumsq epilogue ----------------
#define AST 36
#define BST 72
template <int SRC>
__device__ __forceinline__ void gemm_body(const float* __restrict__ Aext,
                                          const float* __restrict__ B,
                                          float* __restrict__ ss,
                                          int M, int N, int K,
                                          int bx, int nColTiles) {
    const float* A = (SRC == 0) ? Aext : g_buf;
    __shared__ __align__(16) float AsF[2][128 * AST];
    __shared__ __align__(16) float BsF[2][32 * BST];
    const int tid = threadIdx.x;
    const int wid = tid >> 5, lane = tid & 31;
    const int g = lane >> 2, t = lane & 3;
    const int warpM = wid >> 1, warpN = wid & 1;
    const int rowBase = (bx / nColTiles) * 128, colBase = (bx % nColTiles) * 64;

    auto issue = [&](int ch, int buf) {
        const int k0 = ch * 32;
#pragma unroll
        for (int i = 0; i < 4; i++) {
            int f = tid + i * 256;
            int r = f >> 3, c4 = f & 7;
            int gr = rowBase + r, gk = k0 + c4 * 4;
            bool ok = (gr < M) && (gk < K);
            const float* src = ok ? (A + (size_t)gr * K + gk) : A;
            cp_async16(&AsF[buf][r * AST + c4 * 4], src, ok);
        }
#pragma unroll
        for (int i = 0; i < 2; i++) {
            int f = tid + i * 256;
            int r = f >> 4, c4 = f & 15;
            int gk = k0 + r, gn = colBase + c4 * 4;
            bool ok = (gk < K) && (gn < N);
            const float* src = ok ? (B + (size_t)gk * N + gn) : B;
            cp_async16(&BsF[buf][r * BST + c4 * 4], src, ok);
        }
        CP_COMMIT();
    };

    float acc[2][4][4];
#pragma unroll
    for (int mt = 0; mt < 2; mt++)
#pragma unroll
        for (int nt = 0; nt < 4; nt++)
#pragma unroll
            for (int r = 0; r < 4; r++) acc[mt][nt][r] = 0.f;

    const int nCh = (K + 31) / 32;
    issue(0, 0);
    for (int ch = 0; ch < nCh; ch++) {
        const int cur = ch & 1;
        if (ch + 1 < nCh) { issue(ch + 1, cur ^ 1); CP_WAIT(1); }
        else              { CP_WAIT(0); }
        __syncthreads();
#pragma unroll
        for (int kk = 0; kk < 4; kk++) {
            const int kl = kk * 8;
            uint32_t aH[2][4], aL[2][4];
#pragma unroll
            for (int mt = 0; mt < 2; mt++) {
                int m0 = warpM * 32 + mt * 16 + g;
                float a0 = AsF[cur][m0 * AST + kl + t];
                float a1 = AsF[cur][(m0 + 8) * AST + kl + t];
                float a2 = AsF[cur][m0 * AST + kl + t + 4];
                float a3 = AsF[cur][(m0 + 8) * AST + kl + t + 4];
                split_tf32(a0, aH[mt][0], aL[mt][0]);
                split_tf32(a1, aH[mt][1], aL[mt][1]);
                split_tf32(a2, aH[mt][2], aL[mt][2]);
                split_tf32(a3, aH[mt][3], aL[mt][3]);
            }
#pragma unroll
            for (int nt = 0; nt < 4; nt++) {
                int n0 = warpN * 32 + nt * 8 + g;
                float b0 = BsF[cur][(kl + t) * BST + n0];
                float b1 = BsF[cur][(kl + t + 4) * BST + n0];
                uint32_t bH[2], bL[2];
                split_tf32(b0, bH[0], bL[0]);
                split_tf32(b1, bH[1], bL[1]);
#pragma unroll
                for (int mt = 0; mt < 2; mt++) {
                    mma_tf32(acc[mt][nt], aH[mt], bL);
                    mma_tf32(acc[mt][nt], aL[mt], bH);
                    mma_tf32(acc[mt][nt], aH[mt], bH);
                }
            }
        }
        __syncthreads();
    }
#pragma unroll
    for (int mt = 0; mt < 2; mt++) {
#pragma unroll
        for (int half = 0; half < 2; half++) {
            int m = rowBase + warpM * 32 + mt * 16 + g + half * 8;
            float ssp = 0.f;
#pragma unroll
            for (int nt = 0; nt < 4; nt++) {
                int n = colBase + warpN * 32 + nt * 8 + t * 2;
                if (n < N && m < M) {
                    float c0 = acc[mt][nt][half * 2], c1 = acc[mt][nt][half * 2 + 1];
                    *reinterpret_cast<float2*>(g_h + (size_t)m * N + n) = make_float2(c0, c1);
                    ssp += c0 * c0 + c1 * c1;
                }
            }
            ssp += __shfl_xor_sync(0xffffffffu, ssp, 1);
            ssp += __shfl_xor_sync(0xffffffffu, ssp, 2);
            if (t == 0 && m < M) atomicAdd(&ss[m], ssp);
        }
    }
}

// ---------------- kernels ----------------
// fused: [GEMM1 (+ss1) | mask1 gen | edge count]
__global__ void __launch_bounds__(256) k_gemm1_count(const float* __restrict__ x,
                                                     const float* __restrict__ W1,
                                                     const int* __restrict__ dst,
                                                     uint32_t k1a, uint32_t k1b) {
    if (blockIdx.x < GEMM1_BLOCKS) {
        gemm_body<0>(x, W1, g_ss1, N_NODES, H1C, IN_CH, blockIdx.x, GEMM1_NCT);
    } else if (blockIdx.x < GEMM1_BLOCKS + MASK1_BLOCKS) {
        int gwarp = (blockIdx.x - GEMM1_BLOCKS) * 8 + (threadIdx.x >> 5);
        gen_mask(g_mask1, MASK1_WORDS, gwarp, threadIdx.x & 31, k1a, k1b);
    } else {
        int e = (blockIdx.x - GEMM1_BLOCKS - MASK1_BLOCKS) * 256 + threadIdx.x;
        if (e < E_EDGES) atomicAdd(&g_deg[dst[e]], 1);
    }
}

// scan1: local prefix + block sums; also ss1 -> invn.
__global__ void k_scan1() {
    __shared__ int sh[256];
    int b = blockIdx.x, t = threadIdx.x, i = b * 256 + t;
    int v = (i < N_NODES) ? (g_deg[i] + 1) : 0;   // +1 = self-loop
    if (i < N_NODES) g_invn[i] = rsqrtf(fmaxf(g_ss1[i], 1e-24f));
    sh[t] = v;
    __syncthreads();
    for (int off = 1; off < 256; off <<= 1) {
        int x = (t >= off) ? sh[t - off] : 0;
        __syncthreads();
        sh[t] += x;
        __syncthreads();
    }
    if (i < N_NODES) g_rowptr[i] = sh[t] - v;
    if (t == 255) g_bsum[b] = sh[255];
}

// fused: [scan finalize + CSR fill]
__global__ void k_fill(const int* __restrict__ src, const int* __restrict__ dst) {
    __shared__ int sp[256];
    int t = threadIdx.x;
    sp[t] = (t < SCAN_BLOCKS) ? g_bsum[t] : 0;
    __syncthreads();
    for (int off = 1; off < 256; off <<= 1) {
        int x = (t >= off) ? sp[t - off] : 0;
        __syncthreads();
        sp[t] += x;
        __syncthreads();
    }
    int e = blockIdx.x * 256 + t;
    if (blockIdx.x < SCAN_BLOCKS) {
        if (e < N_NODES) {
            int off = (blockIdx.x == 0) ? 0 : sp[blockIdx.x - 1];
            g_rowptr2[e] = g_rowptr[e] + off;
        }
        if (e == 0) g_rowptr2[N_NODES] = E_TOT;
    }
    if (e < N_NODES) g_deg[e] = 0;
    if (e >= E_TOT) return;
    int s, d;
    if (e < E_EDGES) { s = src[e]; d = dst[e]; }
    else             { s = e - E_EDGES; d = s; }
    int blk = d >> 8;
    int off = (blk == 0) ? 0 : sp[blk - 1];
    int pos = atomicAdd(&g_cursor[d], 1);
    g_csrsrc[g_rowptr[d] + off + pos] = s;
}

// fused: [GEMM2 (+ss2) | mask2 gen]
__global__ void __launch_bounds__(256) k_gemm2(const float* __restrict__ W2,
                                               uint32_t k2a, uint32_t k2b) {
    if (blockIdx.x < GEMM2_BLOCKS) {
        gemm_body<1>(nullptr, W2, g_ss2, N_NODES, H2C, H1C, blockIdx.x, GEMM2_NCT);
    } else {
        int gwarp = (blockIdx.x - GEMM2_BLOCKS) * 8 + (threadIdx.x >> 5);
        gen_mask(g_mask2, MASK2_WORDS, gwarp, threadIdx.x & 31, k2a, k2b);
    }
}

// ---------------- fused attention + softmax + agg + relu + dropout ----------
// Warp = one dst node, split into TWO 16-lane groups processing 2 edges/iter.
// Group reduction = 4 shfl stages (shared by 2 edges); cross-group combine at
// the end. Cuts per-edge issue count ~3x vs warp-wide edges.
template <int D, bool USE_INV, bool RESET1>
__global__ void __launch_bounds__(128) k_node(const float* __restrict__ beta_p) {
    const uint32_t* mask = USE_INV ? g_mask1 : g_mask2;
    int v = (blockIdx.x * blockDim.x + threadIdx.x) >> 5;
    int lane = threadIdx.x & 31;
    if (v >= N_NODES) return;
    constexpr int R = (D + 63) / 64;     // float4 regs per lane (16-lane span = 64 floats)
    const int sub = lane & 15;
    const int grp = lane >> 4;           // 0 or 1
    const float4 z4 = make_float4(0.f, 0.f, 0.f, 0.f);
    int vbase = v * D;

    float4 hv[R];
#pragma unroll
    for (int i = 0; i < R; i++) {
        int p = i * 64 + sub * 4;
        hv[i] = (p < D) ? *reinterpret_cast<const float4*>(g_h + vbase + p) : z4;
    }
    float nvv = USE_INV ? g_invn[v] : rsqrtf(fmaxf(g_ss2[v], 1e-24f));
    float bi = __ldg(beta_p) * nvv;
    if (RESET1 && lane == 0) { g_cursor[v] = 0; g_ss1[v] = 0.f; }
    int e0 = g_rowptr2[v], e1 = g_rowptr2[v + 1];
    float denom = 0.0f;
    float4 acc[R];
#pragma unroll
    for (int i = 0; i < R; i++) acc[i] = z4;

    for (int e = e0; e < e1; e += 2) {
        int eg = e + grp;
        bool valid = (eg < e1);
        int s = g_csrsrc[valid ? eg : e];      // e itself always valid
        float ns = USE_INV ? g_invn[s] : rsqrtf(fmaxf(g_ss2[s], 1e-24f));
        int sbase = s * D;
        float4 hs[R];
#pragma unroll
        for (int i = 0; i < R; i++) {
            int p = i * 64 + sub * 4;
            hs[i] = (p < D) ? *reinterpret_cast<const float4*>(g_h + sbase + p) : z4;
        }
        float dot = 0.f;
#pragma unroll
        for (int i = 0; i < R; i++)
            dot += hv[i].x * hs[i].x + hv[i].y * hs[i].y + hv[i].z * hs[i].z + hv[i].w * hs[i].w;
        // reduce within the 16-lane group (offsets 1,2,4,8 stay inside group)
#pragma unroll
        for (int o = 8; o; o >>= 1) dot += __shfl_xor_sync(0xffffffffu, dot, o);
        float w = valid ? __expf(bi * dot * ns) : 0.0f;
        denom += w;
#pragma unroll
        for (int i = 0; i < R; i++) {
            acc[i].x += w * hs[i].x;
            acc[i].y += w * hs[i].y;
            acc[i].z += w * hs[i].z;
            acc[i].w += w * hs[i].w;
        }
    }
    // cross-group combine (offset 16)
    denom += __shfl_xor_sync(0xffffffffu, denom, 16);
#pragma unroll
    for (int i = 0; i < R; i++) {
        acc[i].x += __shfl_xor_sync(0xffffffffu, acc[i].x, 16);
        acc[i].y += __shfl_xor_sync(0xffffffffu, acc[i].y, 16);
        acc[i].z += __shfl_xor_sync(0xffffffffu, acc[i].z, 16);
        acc[i].w += __shfl_xor_sync(0xffffffffu, acc[i].w, 16);
    }
    float dinv = 1.0f / fmaxf(denom, 1e-12f);
    if (grp == 0) {
#pragma unroll
        for (int i = 0; i < R; i++) {
            int p = i * 64 + sub * 4;
            if (p >= D) continue;
            uint32_t idx4 = (uint32_t)(vbase + p);
            uint32_t word = mask[idx4 >> 5];
            uint32_t sh = idx4 & 31u;
            float vals[4] = {acc[i].x * dinv, acc[i].y * dinv, acc[i].z * dinv, acc[i].w * dinv};
            float4 o4;
            float* op = reinterpret_cast<float*>(&o4);
#pragma unroll
            for (int comp = 0; comp < 4; comp++) {
                float val = fmaxf(vals[comp], 0.0f);
                bool keep = (word >> (sh + comp)) & 1u;
                op[comp] = keep ? (val / 0.9f) : 0.0f;
            }
            *reinterpret_cast<float4*>(g_buf + vbase + p) = o4;
        }
    }
}

// ---------------- layer 3 dedicated path (D=2) ----------------
__global__ void k_gemm3_norm(const float* __restrict__ W3) {
    int v = (blockIdx.x * blockDim.x + threadIdx.x) >> 5;
    int lane = threadIdx.x & 31;
    if (v >= N_NODES) return;
    if (lane == 0) g_ss2[v] = 0.f;   // reset for replay
    float s0 = 0.f, s1 = 0.f;
#pragma unroll
    for (int j = 0; j < 4; j++) {
        int d = lane + 32 * j;
        if (d < H2C) {
            float hval = g_buf[v * H2C + d];
            s0 += hval * __ldg(W3 + d * 2 + 0);
            s1 += hval * __ldg(W3 + d * 2 + 1);
        }
    }
#pragma unroll
    for (int o = 16; o; o >>= 1) {
        s0 += __shfl_xor_sync(0xffffffffu, s0, o);
        s1 += __shfl_xor_sync(0xffffffffu, s1, o);
    }
    if (lane == 0) {
        g_h[v * 2 + 0] = s0;
        g_h[v * 2 + 1] = s1;
        g_invn[v] = 1.0f / fmaxf(sqrtf(s0 * s0 + s1 * s1), 1e-12f);
    }
}

__global__ void k_node3(const float* __restrict__ beta_p, float* __restrict__ out) {
    int v = blockIdx.x * blockDim.x + threadIdx.x;
    if (v >= N_NODES) return;
    const float2* h2 = reinterpret_cast<const float2*>(g_h);
    float2 hv = h2[v];
    float bi = __ldg(beta_p) * g_invn[v];
    int e0 = g_rowptr2[v], e1 = g_rowptr2[v + 1];
    float denom = 0.f, a0 = 0.f, a1 = 0.f;
    for (int e = e0; e < e1; e++) {
        int s = g_csrsrc[e];
        float2 hs = h2[s];
        float w = __expf(bi * (hv.x * hs.x + hv.y * hs.y) * g_invn[s]);
        denom += w;
        a0 += w * hs.x;
        a1 += w * hs.y;
    }
    float dinv = 1.0f / fmaxf(denom, 1e-12f);
    out[v * 2 + 0] = fmaxf(a0 * dinv, 0.f);
    out[v * 2 + 1] = fmaxf(a1 * dinv, 0.f);
}

extern "C" void kernel_launch(void* const* d_in, const int* in_sizes, int n_in,
                              void* d_out, int out_size) {
    const float* x  = (const float*)d_in[0];
    const int*   ei = (const int*)d_in[1];
    const float* W1 = (const float*)d_in[2];
    const float* W2 = (const float*)d_in[3];
    const float* W3 = (const float*)d_in[4];
    const float* b1 = (const float*)d_in[5];
    const float* b2 = (const float*)d_in[6];
    const float* b3 = (const float*)d_in[7];
    float* out = (float*)d_out;
    const int* src = ei;
    const int* dst = ei + E_EDGES;

    uint32_t k1a, k1b, k2a, k2b;
    threefry2x32(0u, 42u, 0u, 0u, k1a, k1b);
    threefry2x32(0u, 42u, 0u, 1u, k2a, k2b);

    k_gemm1_count<<<GEMM1_BLOCKS + MASK1_BLOCKS + COUNT_BLOCKS, 256>>>(
        x, W1, dst, k1a, k1b);                                          // 1
    k_scan1<<<SCAN_BLOCKS, 256>>>();                                    // 2
    k_fill<<<FILL_BLOCKS, 256>>>(src, dst);                             // 3
    k_node<H1C, true, true><<<NODE_BLOCKS, 128>>>(b1);                  // 4 <- profiled
    k_gemm2<<<GEMM2_BLOCKS + MASK2_BLOCKS, 256>>>(W2, k2a, k2b);        // 5
    k_node<H2C, false, false><<<NODE_BLOCKS, 128>>>(b2);                // 6
    k_gemm3_norm<<<WNODE_BLOCKS, 256>>>(W3);                            // 7
    k_node3<<<SCAN_BLOCKS, 256>>>(b3, out);                             // 8
    (void)in_sizes; (void)n_in; (void)out_size;
}

// round 17
// speedup vs baseline: 1.0745x; 1.0259x over previous
#include <cuda_runtime.h>
#include <math.h>
#include <stdint.h>

#define N_NODES 50000
#define E_EDGES 800000
#define E_TOT   (E_EDGES + N_NODES)
#define IN_CH 128
#define H1C 200
#define H2C 100
#define OUTC 2

#define GEMM1_NCT    4
#define GEMM1_NRT    391
#define GEMM1_BLOCKS (GEMM1_NCT * GEMM1_NRT)
#define COUNT_BLOCKS 3125
#define GEMM2_NCT    2
#define GEMM2_BLOCKS (GEMM2_NCT * GEMM1_NRT)
#define FILL_BLOCKS  3321
#define NODE_BLOCKS  12500                  // 50000 warps / 4 (128-thread blocks)
#define WNODE_BLOCKS 6250
#define SCAN_BLOCKS  196

#define MASK1_WORDS  (N_NODES * H1C / 32)   // 312500
#define MASK2_WORDS  (N_NODES * H2C / 32)   // 156250
#define MASK1_BLOCKS ((MASK1_WORDS + 255) / 256)  // 1221
#define MASK2_BLOCKS ((MASK2_WORDS + 255) / 256)  // 611

// ---------------- scratch (static __device__, zero-initialized) ----------------
__device__ float g_h[(size_t)N_NODES * H1C];
__device__ float g_buf[(size_t)N_NODES * H1C];
__device__ float g_ss1[N_NODES];            // reset by k_node1
__device__ float g_ss2[N_NODES];            // reset by k_gemm3_norm
__device__ float g_invn[N_NODES];           // layer-1 invn (scan1), then layer-3
__device__ int   g_deg[N_NODES];            // reset by k_fill
__device__ int   g_rowptr[N_NODES];         // LOCAL (per-block) prefix, from scan1
__device__ int   g_rowptr2[N_NODES + 1];    // FINAL rowptr, from k_fill
__device__ int   g_cursor[N_NODES];         // reset by k_node1
__device__ int   g_csrsrc[E_TOT];
__device__ int   g_bsum[256];               // overwritten by scan1 each run
__device__ uint32_t g_mask1[MASK1_WORDS];
__device__ uint32_t g_mask2[MASK2_WORDS];

// ---------------- Threefry-2x32 (matches JAX, confirmed) ----------------
__host__ __device__ inline uint32_t rotl32(uint32_t v, int d) {
    return (v << d) | (v >> (32 - d));
}
__host__ __device__ inline void threefry2x32(uint32_t key0, uint32_t key1,
                                             uint32_t x0, uint32_t x1,
                                             uint32_t& o0, uint32_t& o1) {
    uint32_t ks[3] = {key0, key1, key0 ^ key1 ^ 0x1BD11BDAu};
    const int rot[8] = {13, 15, 26, 6, 17, 29, 16, 24};
    x0 += ks[0]; x1 += ks[1];
#pragma unroll
    for (int i = 0; i < 5; i++) {
        const int* r = &rot[(i & 1) * 4];
#pragma unroll
        for (int j = 0; j < 4; j++) { x0 += x1; x1 = rotl32(x1, r[j]); x1 ^= x0; }
        x0 += ks[(i + 1) % 3];
        x1 += ks[(i + 2) % 3] + (uint32_t)(i + 1);
    }
    o0 = x0; o1 = x1;
}

// Warp-cooperative dropout-mask generation (confirmed R13-R16).
__device__ __forceinline__ void gen_mask(uint32_t* mask, int nwords, int gwarp,
                                         int lane, uint32_t k0, uint32_t k1) {
    int base = gwarp * 32;
    if (base >= nwords) return;
    uint32_t myword = 0;
#pragma unroll 4
    for (int k = 0; k < 32; k++) {
        uint32_t idx = (uint32_t)(base + k) * 32u + (uint32_t)lane;
        uint32_t o0, o1;
        threefry2x32(k0, k1, 0u, idx, o0, o1);
        uint32_t bits = o0 ^ o1;
        float u = __uint_as_float((bits >> 9) | 0x3f800000u) - 1.0f;
        uint32_t b = __ballot_sync(0xffffffffu, u < 0.9f);
        if (lane == k) myword = b;
    }
    if (base + lane < nwords) mask[base + lane] = myword;
}

// ---------------- cp.async helpers ----------------
__device__ __forceinline__ void cp_async16(void* smem_dst, const void* gsrc, bool valid) {
    uint32_t saddr = (uint32_t)__cvta_generic_to_shared(smem_dst);
    int bytes = valid ? 16 : 0;
    asm volatile("cp.async.cg.shared.global [%0], [%1], 16, %2;\n"
                 :: "r"(saddr), "l"(gsrc), "r"(bytes));
}
#define CP_COMMIT()  asm volatile("cp.async.commit_group;\n")
#define CP_WAIT(n)   asm volatile("cp.async.wait_group %0;\n" :: "n"(n))

// ---------------- tf32 helpers ----------------
__device__ __forceinline__ uint32_t f2tf32(float f) {
    uint32_t o;
    asm volatile("cvt.rna.tf32.f32 %0, %1;" : "=r"(o) : "f"(f));
    return o;
}
__device__ __forceinline__ void split_tf32(float f, uint32_t& hi, uint32_t& lo) {
    hi = f2tf32(f);
    lo = f2tf32(f - __uint_as_float(hi));
}
__device__ __forceinline__ void mma_tf32(float* c, const uint32_t* a, const uint32_t* b) {
    asm volatile(
        "mma.sync.aligned.m16n8k8.row.col.f32.tf32.tf32.f32 "
        "{%0,%1,%2,%3}, {%4,%5,%6,%7}, {%8,%9}, {%0,%1,%2,%3};\n"
        : "+f"(c[0]), "+f"(c[1]), "+f"(c[2]), "+f"(c[3])
        : "r"(a[0]), "r"(a[1]), "r"(a[2]), "r"(a[3]), "r"(b[0]), "r"(b[1]));
}

// ---------------- 3xTF32 GEMM body + fused row-sumsq epilogue ----------------
#define AST 36
#define BST 72
template <int SRC>
__device__ __forceinline__ void gemm_body(const float* __restrict__ Aext,
                                          const float* __restrict__ B,
                                          float* __restrict__ ss,
                                          int M, int N, int K,
                                          int bx, int nColTiles) {
    const float* A = (SRC == 0) ? Aext : g_buf;
    __shared__ __align__(16) float AsF[2][128 * AST];
    __shared__ __align__(16) float BsF[2][32 * BST];
    const int tid = threadIdx.x;
    const int wid = tid >> 5, lane = tid & 31;
    const int g = lane >> 2, t = lane & 3;
    const int warpM = wid >> 1, warpN = wid & 1;
    const int rowBase = (bx / nColTiles) * 128, colBase = (bx % nColTiles) * 64;

    auto issue = [&](int ch, int buf) {
        const int k0 = ch * 32;
#pragma unroll
        for (int i = 0; i < 4; i++) {
            int f = tid + i * 256;
            int r = f >> 3, c4 = f & 7;
            int gr = rowBase + r, gk = k0 + c4 * 4;
            bool ok = (gr < M) && (gk < K);
            const float* src = ok ? (A + (size_t)gr * K + gk) : A;
            cp_async16(&AsF[buf][r * AST + c4 * 4], src, ok);
        }
#pragma unroll
        for (int i = 0; i < 2; i++) {
            int f = tid + i * 256;
            int r = f >> 4, c4 = f & 15;
            int gk = k0 + r, gn = colBase + c4 * 4;
            bool ok = (gk < K) && (gn < N);
            const float* src = ok ? (B + (size_t)gk * N + gn) : B;
            cp_async16(&BsF[buf][r * BST + c4 * 4], src, ok);
        }
        CP_COMMIT();
    };

    float acc[2][4][4];
#pragma unroll
    for (int mt = 0; mt < 2; mt++)
#pragma unroll
        for (int nt = 0; nt < 4; nt++)
#pragma unroll
            for (int r = 0; r < 4; r++) acc[mt][nt][r] = 0.f;

    const int nCh = (K + 31) / 32;
    issue(0, 0);
    for (int ch = 0; ch < nCh; ch++) {
        const int cur = ch & 1;
        if (ch + 1 < nCh) { issue(ch + 1, cur ^ 1); CP_WAIT(1); }
        else              { CP_WAIT(0); }
        __syncthreads();
#pragma unroll
        for (int kk = 0; kk < 4; kk++) {
            const int kl = kk * 8;
            uint32_t aH[2][4], aL[2][4];
#pragma unroll
            for (int mt = 0; mt < 2; mt++) {
                int m0 = warpM * 32 + mt * 16 + g;
                float a0 = AsF[cur][m0 * AST + kl + t];
                float a1 = AsF[cur][(m0 + 8) * AST + kl + t];
                float a2 = AsF[cur][m0 * AST + kl + t + 4];
                float a3 = AsF[cur][(m0 + 8) * AST + kl + t + 4];
                split_tf32(a0, aH[mt][0], aL[mt][0]);
                split_tf32(a1, aH[mt][1], aL[mt][1]);
                split_tf32(a2, aH[mt][2], aL[mt][2]);
                split_tf32(a3, aH[mt][3], aL[mt][3]);
            }
#pragma unroll
            for (int nt = 0; nt < 4; nt++) {
                int n0 = warpN * 32 + nt * 8 + g;
                float b0 = BsF[cur][(kl + t) * BST + n0];
                float b1 = BsF[cur][(kl + t + 4) * BST + n0];
                uint32_t bH[2], bL[2];
                split_tf32(b0, bH[0], bL[0]);
                split_tf32(b1, bH[1], bL[1]);
#pragma unroll
                for (int mt = 0; mt < 2; mt++) {
                    mma_tf32(acc[mt][nt], aH[mt], bL);
                    mma_tf32(acc[mt][nt], aL[mt], bH);
                    mma_tf32(acc[mt][nt], aH[mt], bH);
                }
            }
        }
        __syncthreads();
    }
#pragma unroll
    for (int mt = 0; mt < 2; mt++) {
#pragma unroll
        for (int half = 0; half < 2; half++) {
            int m = rowBase + warpM * 32 + mt * 16 + g + half * 8;
            float ssp = 0.f;
#pragma unroll
            for (int nt = 0; nt < 4; nt++) {
                int n = colBase + warpN * 32 + nt * 8 + t * 2;
                if (n < N && m < M) {
                    float c0 = acc[mt][nt][half * 2], c1 = acc[mt][nt][half * 2 + 1];
                    *reinterpret_cast<float2*>(g_h + (size_t)m * N + n) = make_float2(c0, c1);
                    ssp += c0 * c0 + c1 * c1;
                }
            }
            ssp += __shfl_xor_sync(0xffffffffu, ssp, 1);
            ssp += __shfl_xor_sync(0xffffffffu, ssp, 2);
            if (t == 0 && m < M) atomicAdd(&ss[m], ssp);
        }
    }
}

// ---------------- kernels ----------------
// fused: [GEMM1 (+ss1) | mask1 gen | edge count]
__global__ void __launch_bounds__(256) k_gemm1_count(const float* __restrict__ x,
                                                     const float* __restrict__ W1,
                                                     const int* __restrict__ dst,
                                                     uint32_t k1a, uint32_t k1b) {
    if (blockIdx.x < GEMM1_BLOCKS) {
        gemm_body<0>(x, W1, g_ss1, N_NODES, H1C, IN_CH, blockIdx.x, GEMM1_NCT);
    } else if (blockIdx.x < GEMM1_BLOCKS + MASK1_BLOCKS) {
        int gwarp = (blockIdx.x - GEMM1_BLOCKS) * 8 + (threadIdx.x >> 5);
        gen_mask(g_mask1, MASK1_WORDS, gwarp, threadIdx.x & 31, k1a, k1b);
    } else {
        int e = (blockIdx.x - GEMM1_BLOCKS - MASK1_BLOCKS) * 256 + threadIdx.x;
        if (e < E_EDGES) atomicAdd(&g_deg[dst[e]], 1);
    }
}

// scan1: local prefix + block sums; also ss1 -> invn.
__global__ void k_scan1() {
    __shared__ int sh[256];
    int b = blockIdx.x, t = threadIdx.x, i = b * 256 + t;
    int v = (i < N_NODES) ? (g_deg[i] + 1) : 0;   // +1 = self-loop
    if (i < N_NODES) g_invn[i] = rsqrtf(fmaxf(g_ss1[i], 1e-24f));
    sh[t] = v;
    __syncthreads();
    for (int off = 1; off < 256; off <<= 1) {
        int x = (t >= off) ? sh[t - off] : 0;
        __syncthreads();
        sh[t] += x;
        __syncthreads();
    }
    if (i < N_NODES) g_rowptr[i] = sh[t] - v;
    if (t == 255) g_bsum[b] = sh[255];
}

// fused: [scan finalize + CSR fill]
__global__ void k_fill(const int* __restrict__ src, const int* __restrict__ dst) {
    __shared__ int sp[256];
    int t = threadIdx.x;
    sp[t] = (t < SCAN_BLOCKS) ? g_bsum[t] : 0;
    __syncthreads();
    for (int off = 1; off < 256; off <<= 1) {
        int x = (t >= off) ? sp[t - off] : 0;
        __syncthreads();
        sp[t] += x;
        __syncthreads();
    }
    int e = blockIdx.x * 256 + t;
    if (blockIdx.x < SCAN_BLOCKS) {
        if (e < N_NODES) {
            int off = (blockIdx.x == 0) ? 0 : sp[blockIdx.x - 1];
            g_rowptr2[e] = g_rowptr[e] + off;
        }
        if (e == 0) g_rowptr2[N_NODES] = E_TOT;
    }
    if (e < N_NODES) g_deg[e] = 0;
    if (e >= E_TOT) return;
    int s, d;
    if (e < E_EDGES) { s = src[e]; d = dst[e]; }
    else             { s = e - E_EDGES; d = s; }
    int blk = d >> 8;
    int off = (blk == 0) ? 0 : sp[blk - 1];
    int pos = atomicAdd(&g_cursor[d], 1);
    g_csrsrc[g_rowptr[d] + off + pos] = s;
}

// fused: [GEMM2 (+ss2) | mask2 gen]
__global__ void __launch_bounds__(256) k_gemm2(const float* __restrict__ W2,
                                               uint32_t k2a, uint32_t k2b) {
    if (blockIdx.x < GEMM2_BLOCKS) {
        gemm_body<1>(nullptr, W2, g_ss2, N_NODES, H2C, H1C, blockIdx.x, GEMM2_NCT);
    } else {
        int gwarp = (blockIdx.x - GEMM2_BLOCKS) * 8 + (threadIdx.x >> 5);
        gen_mask(g_mask2, MASK2_WORDS, gwarp, threadIdx.x & 31, k2a, k2b);
    }
}

// ---- node layer 1 (D=200): warp-wide rows, unroll-2 (R15-proven, 94.5us) ----
__global__ void __launch_bounds__(128) k_node1(const float* __restrict__ beta_p) {
    constexpr int D = H1C;
    int v = (blockIdx.x * blockDim.x + threadIdx.x) >> 5;
    int lane = threadIdx.x & 31;
    if (v >= N_NODES) return;
    constexpr int C4 = (D + 127) / 128;   // 2
    const float4 z4 = make_float4(0.f, 0.f, 0.f, 0.f);

    float4 hv[C4];
    int vbase = v * D;
#pragma unroll
    for (int c = 0; c < C4; c++) {
        int f0 = (c * 32 + lane) * 4;
        hv[c] = (f0 < D) ? *reinterpret_cast<const float4*>(g_h + vbase + f0) : z4;
    }
    float bi = __ldg(beta_p) * g_invn[v];
    if (lane == 0) { g_cursor[v] = 0; g_ss1[v] = 0.f; }   // replay resets
    int e0 = g_rowptr2[v], e1 = g_rowptr2[v + 1];
    float denom = 0.0f;
    float4 acc[C4];
#pragma unroll
    for (int c = 0; c < C4; c++) acc[c] = z4;

    for (int e = e0; e < e1; e += 2) {
        bool hasB = (e + 1 < e1);
        int sA = g_csrsrc[e];
        int sB = hasB ? g_csrsrc[e + 1] : sA;
        float nA = g_invn[sA], nB = g_invn[sB];
        int aBase = sA * D, bBase = sB * D;
        float4 hA[C4], hB[C4];
#pragma unroll
        for (int c = 0; c < C4; c++) {
            int f0 = (c * 32 + lane) * 4;
            bool ok = (f0 < D);
            hA[c] = ok ? *reinterpret_cast<const float4*>(g_h + aBase + f0) : z4;
            hB[c] = ok ? *reinterpret_cast<const float4*>(g_h + bBase + f0) : z4;
        }
        float dA = 0.f, dB = 0.f;
#pragma unroll
        for (int c = 0; c < C4; c++) {
            dA += hv[c].x * hA[c].x + hv[c].y * hA[c].y + hv[c].z * hA[c].z + hv[c].w * hA[c].w;
            dB += hv[c].x * hB[c].x + hv[c].y * hB[c].y + hv[c].z * hB[c].z + hv[c].w * hB[c].w;
        }
#pragma unroll
        for (int o = 16; o; o >>= 1) {
            dA += __shfl_xor_sync(0xffffffffu, dA, o);
            dB += __shfl_xor_sync(0xffffffffu, dB, o);
        }
        float wA = __expf(bi * dA * nA);
        float wB = hasB ? __expf(bi * dB * nB) : 0.0f;
        denom += wA + wB;
#pragma unroll
        for (int c = 0; c < C4; c++) {
            acc[c].x += wA * hA[c].x + wB * hB[c].x;
            acc[c].y += wA * hA[c].y + wB * hB[c].y;
            acc[c].z += wA * hA[c].z + wB * hB[c].z;
            acc[c].w += wA * hA[c].w + wB * hB[c].w;
        }
    }
    float dinv = 1.0f / fmaxf(denom, 1e-12f);
#pragma unroll
    for (int c = 0; c < C4; c++) {
        int f0 = (c * 32 + lane) * 4;
        if (f0 >= D) continue;
        uint32_t idx4 = (uint32_t)(vbase + f0);
        uint32_t word = g_mask1[idx4 >> 5];
        uint32_t sh = idx4 & 31u;
        float vals[4] = {acc[c].x * dinv, acc[c].y * dinv, acc[c].z * dinv, acc[c].w * dinv};
        float4 o4;
        float* op = reinterpret_cast<float*>(&o4);
#pragma unroll
        for (int comp = 0; comp < 4; comp++) {
            float val = fmaxf(vals[comp], 0.0f);
            bool keep = (word >> (sh + comp)) & 1u;
            op[comp] = keep ? (val / 0.9f) : 0.0f;
        }
        *reinterpret_cast<float4*>(g_buf + vbase + f0) = o4;
    }
}

// ---- node layer 2 (D=100): split-warp, two 16-lane edge groups (R16) ----
__global__ void __launch_bounds__(128) k_node2(const float* __restrict__ beta_p) {
    constexpr int D = H2C;
    int v = (blockIdx.x * blockDim.x + threadIdx.x) >> 5;
    int lane = threadIdx.x & 31;
    if (v >= N_NODES) return;
    constexpr int R = (D + 63) / 64;      // 2
    const int sub = lane & 15;
    const int grp = lane >> 4;
    const float4 z4 = make_float4(0.f, 0.f, 0.f, 0.f);
    int vbase = v * D;

    float4 hv[R];
#pragma unroll
    for (int i = 0; i < R; i++) {
        int p = i * 64 + sub * 4;
        hv[i] = (p < D) ? *reinterpret_cast<const float4*>(g_h + vbase + p) : z4;
    }
    float bi = __ldg(beta_p) * rsqrtf(fmaxf(g_ss2[v], 1e-24f));
    int e0 = g_rowptr2[v], e1 = g_rowptr2[v + 1];
    float denom = 0.0f;
    float4 acc[R];
#pragma unroll
    for (int i = 0; i < R; i++) acc[i] = z4;

    for (int e = e0; e < e1; e += 2) {
        int eg = e + grp;
        bool valid = (eg < e1);
        int s = g_csrsrc[valid ? eg : e];
        float ns = rsqrtf(fmaxf(g_ss2[s], 1e-24f));
        int sbase = s * D;
        float4 hs[R];
#pragma unroll
        for (int i = 0; i < R; i++) {
            int p = i * 64 + sub * 4;
            hs[i] = (p < D) ? *reinterpret_cast<const float4*>(g_h + sbase + p) : z4;
        }
        float dot = 0.f;
#pragma unroll
        for (int i = 0; i < R; i++)
            dot += hv[i].x * hs[i].x + hv[i].y * hs[i].y + hv[i].z * hs[i].z + hv[i].w * hs[i].w;
#pragma unroll
        for (int o = 8; o; o >>= 1) dot += __shfl_xor_sync(0xffffffffu, dot, o);
        float w = valid ? __expf(bi * dot * ns) : 0.0f;
        denom += w;
#pragma unroll
        for (int i = 0; i < R; i++) {
            acc[i].x += w * hs[i].x;
            acc[i].y += w * hs[i].y;
            acc[i].z += w * hs[i].z;
            acc[i].w += w * hs[i].w;
        }
    }
    denom += __shfl_xor_sync(0xffffffffu, denom, 16);
#pragma unroll
    for (int i = 0; i < R; i++) {
        acc[i].x += __shfl_xor_sync(0xffffffffu, acc[i].x, 16);
        acc[i].y += __shfl_xor_sync(0xffffffffu, acc[i].y, 16);
        acc[i].z += __shfl_xor_sync(0xffffffffu, acc[i].z, 16);
        acc[i].w += __shfl_xor_sync(0xffffffffu, acc[i].w, 16);
    }
    float dinv = 1.0f / fmaxf(denom, 1e-12f);
    if (grp == 0) {
#pragma unroll
        for (int i = 0; i < R; i++) {
            int p = i * 64 + sub * 4;
            if (p >= D) continue;
            uint32_t idx4 = (uint32_t)(vbase + p);
            uint32_t word = g_mask2[idx4 >> 5];
            uint32_t sh = idx4 & 31u;
            float vals[4] = {acc[i].x * dinv, acc[i].y * dinv, acc[i].z * dinv, acc[i].w * dinv};
            float4 o4;
            float* op = reinterpret_cast<float*>(&o4);
#pragma unroll
            for (int comp = 0; comp < 4; comp++) {
                float val = fmaxf(vals[comp], 0.0f);
                bool keep = (word >> (sh + comp)) & 1u;
                op[comp] = keep ? (val / 0.9f) : 0.0f;
            }
            *reinterpret_cast<float4*>(g_buf + vbase + p) = o4;
        }
    }
}

// ---------------- layer 3 dedicated path (D=2) ----------------
__global__ void k_gemm3_norm(const float* __restrict__ W3) {
    int v = (blockIdx.x * blockDim.x + threadIdx.x) >> 5;
    int lane = threadIdx.x & 31;
    if (v >= N_NODES) return;
    if (lane == 0) g_ss2[v] = 0.f;   // reset for replay
    float s0 = 0.f, s1 = 0.f;
#pragma unroll
    for (int j = 0; j < 4; j++) {
        int d = lane + 32 * j;
        if (d < H2C) {
            float hval = g_buf[v * H2C + d];
            s0 += hval * __ldg(W3 + d * 2 + 0);
            s1 += hval * __ldg(W3 + d * 2 + 1);
        }
    }
#pragma unroll
    for (int o = 16; o; o >>= 1) {
        s0 += __shfl_xor_sync(0xffffffffu, s0, o);
        s1 += __shfl_xor_sync(0xffffffffu, s1, o);
    }
    if (lane == 0) {
        g_h[v * 2 + 0] = s0;
        g_h[v * 2 + 1] = s1;
        g_invn[v] = 1.0f / fmaxf(sqrtf(s0 * s0 + s1 * s1), 1e-12f);
    }
}

__global__ void k_node3(const float* __restrict__ beta_p, float* __restrict__ out) {
    int v = blockIdx.x * blockDim.x + threadIdx.x;
    if (v >= N_NODES) return;
    const float2* h2 = reinterpret_cast<const float2*>(g_h);
    float2 hv = h2[v];
    float bi = __ldg(beta_p) * g_invn[v];
    int e0 = g_rowptr2[v], e1 = g_rowptr2[v + 1];
    float denom = 0.f, a0 = 0.f, a1 = 0.f;
    for (int e = e0; e < e1; e++) {
        int s = g_csrsrc[e];
        float2 hs = h2[s];
        float w = __expf(bi * (hv.x * hs.x + hv.y * hs.y) * g_invn[s]);
        denom += w;
        a0 += w * hs.x;
        a1 += w * hs.y;
    }
    float dinv = 1.0f / fmaxf(denom, 1e-12f);
    out[v * 2 + 0] = fmaxf(a0 * dinv, 0.f);
    out[v * 2 + 1] = fmaxf(a1 * dinv, 0.f);
}

extern "C" void kernel_launch(void* const* d_in, const int* in_sizes, int n_in,
                              void* d_out, int out_size) {
    const float* x  = (const float*)d_in[0];
    const int*   ei = (const int*)d_in[1];
    const float* W1 = (const float*)d_in[2];
    const float* W2 = (const float*)d_in[3];
    const float* W3 = (const float*)d_in[4];
    const float* b1 = (const float*)d_in[5];
    const float* b2 = (const float*)d_in[6];
    const float* b3 = (const float*)d_in[7];
    float* out = (float*)d_out;
    const int* src = ei;
    const int* dst = ei + E_EDGES;

    uint32_t k1a, k1b, k2a, k2b;
    threefry2x32(0u, 42u, 0u, 0u, k1a, k1b);
    threefry2x32(0u, 42u, 0u, 1u, k2a, k2b);

    k_gemm1_count<<<GEMM1_BLOCKS + MASK1_BLOCKS + COUNT_BLOCKS, 256>>>(
        x, W1, dst, k1a, k1b);                                          // 1
    k_scan1<<<SCAN_BLOCKS, 256>>>();                                    // 2
    k_fill<<<FILL_BLOCKS, 256>>>(src, dst);                             // 3
    k_node1<<<NODE_BLOCKS, 128>>>(b1);                                  // 4 <- profiled
    k_gemm2<<<GEMM2_BLOCKS + MASK2_BLOCKS, 256>>>(W2, k2a, k2b);        // 5
    k_node2<<<NODE_BLOCKS, 128>>>(b2);                                  // 6
    k_gemm3_norm<<<WNODE_BLOCKS, 256>>>(W3);                            // 7
    k_node3<<<SCAN_BLOCKS, 256>>>(b3, out);                             // 8
    (void)in_sizes; (void)n_in; (void)out_size;
}